// round 15
// baseline (speedup 1.0000x reference)
#include <cuda_runtime.h>
#include <cuda_fp16.h>
#include <math.h>
#include <stdint.h>

// Problem dims
#define Bc   64
#define Pc   196
#define Sc   22
#define Tc   21
#define Vc   10000
#define Ec   512
#define Ac   512
#define Uc   512
#define ENCc 2048
#define N4U  2048   // 4*U
#define CBN  2560   // A + ENC (att2 | beta combined)
#define KX   2560   // E + ENC (W_x K dim)
#define NB   131    // persistent grid size (single wave on 148 SMs)

// ---------------- scratch (static __device__ arrays; no allocation) -------------
__device__ __half g_ench[Bc * Pc * ENCc];     // sorted encoder fp16 (51.4 MB)
__device__ __half g_att1h[Bc * Pc * Ac];      // att1 fp16 (12.8 MB)
__device__ __half g_Waet[Ac * ENCc];          // W_att_enc^T
__device__ __half g_Wcbt[CBN * Uc];           // [Wag|Wbeta]^T
__device__ __half g_Woutt[Vc * Uc];           // W_out^T
__device__ __half g_Wxt[N4U * KX];            // W_x^T
__device__ __half g_Wht[N4U * Uc];            // W_h^T
__device__ __half g_embh[Tc * Bc * Ec];       // embeddings fp16, all steps
__device__ __half g_ch[Bc * Uc];              // c fp16 (GEMM A operand)
__device__ __half g_hh[Bc * Uc];              // h fp16
__device__ __half g_chist[Tc * Bc * Uc];      // c after each step (fp16, for logits)
__device__ __half g_aweh[Bc * ENCc];          // gated context fp16
__device__ float g_mean[Bc * ENCc];
__device__ float g_h[Bc * Uc];
__device__ float g_c[Bc * Uc];
__device__ float g_cb[Bc * CBN];              // [att2 | beta-logits] (no bias)
__device__ float g_zp[16 * Bc * Uc > 10 * Bc * N4U ? 16 * Bc * Uc : 10 * Bc * N4U];
__device__ float g_zpe[Tc * Bc * N4U];        // precomputed emb@Wx for all steps (11MB)
__device__ float g_logitsA[Tc * Bc * Vc];     // logits for all steps (53.8MB)
__device__ int   g_order[Bc];
__device__ int   g_ilen[Bc];
__device__ int   g_nb[Tc];                    // active rows per step
__device__ int   g_seqs[Bc * Sc];

// ---------------- parallel-flag grid barrier (replay-safe, monotonic) -------------
__device__ volatile int g_flags[NB];
__device__ volatile int g_gen;

__device__ __forceinline__ void grid_bar() {
    __syncthreads();
    int gen = g_gen;
    if (blockIdx.x == 0) {
        if (threadIdx.x == 0) {
            __threadfence();
            g_flags[0] = gen + 1;
        }
        if (threadIdx.x < NB) {
            while (g_flags[threadIdx.x] < gen + 1) {}
        }
        __syncthreads();
        if (threadIdx.x == 0) {
            __threadfence();
            g_gen = gen + 1;
        }
    } else {
        if (threadIdx.x == 0) {
            __threadfence();
            g_flags[blockIdx.x] = gen + 1;
            while (g_gen < gen + 1) {}
            __threadfence();
        }
    }
    __syncthreads();
}

// ---------------- sort: stable argsort(-lens); also per-step active counts --------
__global__ void sort_kernel(const int* __restrict__ lens,
                            const int* __restrict__ seqs,
                            float* __restrict__ out_seqs,
                            float* __restrict__ out_ilen,
                            float* __restrict__ out_order) {
    int tid = threadIdx.x;  // 64 threads
    __shared__ int s_len[Bc];
    s_len[tid] = lens[tid];
    __syncthreads();
    int myL = s_len[tid];
    int rank = 0;
    for (int j = 0; j < Bc; j++) {
        int lj = s_len[j];
        rank += (lj > myL) || (lj == myL && j < tid);
    }
    g_order[rank] = tid;
    __syncthreads();
    int src = g_order[tid];
    int il = s_len[src] - 1;
    g_ilen[tid] = il;
    out_ilen[tid] = (float)il;
    out_order[tid] = (float)src;
    for (int s = 0; s < Sc; s++) {
        int v = seqs[src * Sc + s];
        g_seqs[tid * Sc + s] = v;
        out_seqs[tid * Sc + s] = (float)v;
    }
    __syncthreads();
    if (tid < Tc) {
        int cnt = 0;
        for (int b = 0; b < Bc; b++) cnt += (g_ilen[b] > tid) ? 1 : 0;
        g_nb[tid] = cnt;
    }
}

// ---------------- zero predictions + alphas once (masked slots stay zero) ---------
__global__ void zero_out_kernel(float* __restrict__ out_pred,
                                float* __restrict__ out_alpha) {
    size_t i = (size_t)blockIdx.x * 256 + threadIdx.x;
    float4 z = {0, 0, 0, 0};
    const size_t NP = (size_t)Bc * Tc * Vc / 4;
    const size_t NA = (size_t)Bc * Tc * Pc / 4;
    if (i < NP) ((float4*)out_pred)[i] = z;
    else if (i < NP + NA) ((float4*)out_alpha)[i - NP] = z;
}

// ---------------- permute encoder rows -> fp16 sorted copy ------------------------
__global__ void permute_kernel(const float* __restrict__ enc) {
    int b = blockIdx.x, p = blockIdx.y;
    int src = g_order[b];
    const float4* s = (const float4*)&enc[((size_t)src * Pc + p) * ENCc];
    __half2* dh = (__half2*)&g_ench[((size_t)b * Pc + p) * ENCc];
    for (int i = threadIdx.x; i < ENCc / 4; i += 256) {
        float4 v = s[i];
        dh[i * 2 + 0] = __floats2half2_rn(v.x, v.y);
        dh[i * 2 + 1] = __floats2half2_rn(v.z, v.w);
    }
}

// ---------------- precompute embeddings (fp16) for all timesteps ------------------
__global__ void emb_all_kernel(const float* __restrict__ emb_table) {
    int b = blockIdx.x, t = blockIdx.y;  // 128 threads
    int tok = g_seqs[b * Sc + t];
    float4 v = ((const float4*)(emb_table + (size_t)tok * Ec))[threadIdx.x];
    __half2 h0 = __floats2half2_rn(v.x, v.y);
    __half2 h1 = __floats2half2_rn(v.z, v.w);
    __half2* dst = (__half2*)(g_embh + ((size_t)t * Bc + b) * Ec);
    dst[threadIdx.x * 2 + 0] = h0;
    dst[threadIdx.x * 2 + 1] = h1;
}

// ---------------- mean over pixels (from fp16 copy, fp32 accum) -------------------
__global__ void mean_kernel() {
    int b = blockIdx.x;
    int e0 = blockIdx.y * 1024 + threadIdx.x * 4;
    const __half* encb = g_ench + (size_t)b * Pc * ENCc + e0;
    float4 a0 = {0,0,0,0}, a1 = {0,0,0,0}, a2 = {0,0,0,0}, a3 = {0,0,0,0};
    for (int p = 0; p < Pc; p += 4) {
        uint2 r0 = *(const uint2*)(encb + (size_t)(p + 0) * ENCc);
        uint2 r1 = *(const uint2*)(encb + (size_t)(p + 1) * ENCc);
        uint2 r2 = *(const uint2*)(encb + (size_t)(p + 2) * ENCc);
        uint2 r3 = *(const uint2*)(encb + (size_t)(p + 3) * ENCc);
        float2 f;
        f = __half22float2(*(__half2*)&r0.x); a0.x += f.x; a0.y += f.y;
        f = __half22float2(*(__half2*)&r0.y); a0.z += f.x; a0.w += f.y;
        f = __half22float2(*(__half2*)&r1.x); a1.x += f.x; a1.y += f.y;
        f = __half22float2(*(__half2*)&r1.y); a1.z += f.x; a1.w += f.y;
        f = __half22float2(*(__half2*)&r2.x); a2.x += f.x; a2.y += f.y;
        f = __half22float2(*(__half2*)&r2.y); a2.z += f.x; a2.w += f.y;
        f = __half22float2(*(__half2*)&r3.x); a3.x += f.x; a3.y += f.y;
        f = __half22float2(*(__half2*)&r3.y); a3.z += f.x; a3.w += f.y;
    }
    float4 r;
    r.x = (a0.x + a1.x + a2.x + a3.x) * (1.0f / Pc);
    r.y = (a0.y + a1.y + a2.y + a3.y) * (1.0f / Pc);
    r.z = (a0.z + a1.z + a2.z + a3.z) * (1.0f / Pc);
    r.w = (a0.w + a1.w + a2.w + a3.w) * (1.0f / Pc);
    *(float4*)(g_mean + (size_t)b * ENCc + e0) = r;
}

// ---------------- transpose-convert tile fp32[K,N] -> fp16[N,K] -------------------
__device__ void conv_tile(const float* __restrict__ in, __half* __restrict__ out,
                          int K, int N, int tidx) {
    __shared__ float tile[32][33];
    int gx = (N + 31) >> 5;
    int n0 = (tidx % gx) * 32, k0 = (tidx / gx) * 32;
    int tx = threadIdx.x & 31, ty = threadIdx.x >> 5;  // 256 thr
#pragma unroll
    for (int i = 0; i < 32; i += 8) {
        int k = k0 + ty + i, n = n0 + tx;
        tile[ty + i][tx] = (n < N) ? in[(size_t)k * N + n] : 0.f;
    }
    __syncthreads();
#pragma unroll
    for (int i = 0; i < 32; i += 8) {
        int n = n0 + ty + i;
        if (n < N) out[(size_t)n * K + k0 + tx] = __float2half(tile[tx][ty + i]);
    }
}

__global__ __launch_bounds__(256) void convT_all(
    const float* __restrict__ Wae, const float* __restrict__ Wag,
    const float* __restrict__ Wbeta, const float* __restrict__ Wout,
    const float* __restrict__ Wx, const float* __restrict__ Wh) {
    int b = blockIdx.x;
    if      (b < 1024)  conv_tile(Wae,   g_Waet,                  ENCc, Ac,   b);
    else if (b < 1280)  conv_tile(Wag,   g_Wcbt,                  Uc,   Ac,   b - 1024);
    else if (b < 2304)  conv_tile(Wbeta, g_Wcbt + (size_t)Ac*Uc,  Uc,   ENCc, b - 1280);
    else if (b < 7312)  conv_tile(Wout,  g_Woutt,                 Uc,   Vc,   b - 2304);
    else if (b < 12432) conv_tile(Wx,    g_Wxt,                   KX,   N4U,  b - 7312);
    else                conv_tile(Wh,    g_Wht,                   Uc,   N4U,  b - 12432);
}

// ---------------- fp16 MMA helper --------------------------------------------------
__device__ __forceinline__ void mma_fp16(float* c, const uint32_t* a, const uint32_t* b) {
    asm volatile(
        "mma.sync.aligned.m16n8k16.row.col.f32.f16.f16.f32 "
        "{%0,%1,%2,%3}, {%4,%5,%6,%7}, {%8,%9}, {%0,%1,%2,%3};"
        : "+f"(c[0]), "+f"(c[1]), "+f"(c[2]), "+f"(c[3])
        : "r"(a[0]), "r"(a[1]), "r"(a[2]), "r"(a[3]), "r"(b[0]), "r"(b[1]));
}

// ---- 64x128-tile fp16 GEMM, smem double-buffered, M-adaptive ----------------------
template <bool HOUT>
__device__ void fp16_gemm(const __half* __restrict__ A, int lda,
                          const __half* __restrict__ Wt, int ldk,
                          void* __restrict__ Cv, int ldc,
                          int K, int nguard, const float* __restrict__ bias,
                          __half* __restrict__ sA, __half* __restrict__ sW,
                          int half) {
    const int tid = threadIdx.x;
    const int warp = tid >> 5, lane = tid & 31;
    const int wm = (warp >> 2) << 5;
    const int wn = (warp & 3) << 5;
    const bool act = !(half && wm);

    float acc[2][4][4];
#pragma unroll
    for (int i = 0; i < 2; i++)
#pragma unroll
        for (int j = 0; j < 4; j++)
#pragma unroll
            for (int q = 0; q < 4; q++) acc[i][j][q] = 0.f;

    const int ar = tid >> 2, akq = (tid & 3) << 3;
    const int nr = tid >> 1, koff = (tid & 1) << 4;
    const bool wok = nr < nguard;

    uint4 a_reg = __ldcg((const uint4*)(A + (size_t)ar * lda + akq));
    uint4 w_reg0 = {0, 0, 0, 0}, w_reg1 = {0, 0, 0, 0};
    if (wok) {
        const __half* wp = Wt + (size_t)nr * ldk + koff;
        w_reg0 = *(const uint4*)wp;
        w_reg1 = *(const uint4*)(wp + 8);
    }

    int buf = 0;
    for (int k0 = 0; k0 < K; k0 += 32) {
        __half* cA = sA + buf * (64 * 40);
        __half* cW = sW + buf * (128 * 40);
        *(uint4*)&cA[ar * 40 + akq] = a_reg;
        *(uint4*)&cW[nr * 40 + koff] = w_reg0;
        *(uint4*)&cW[nr * 40 + koff + 8] = w_reg1;
        __syncthreads();
        int k1 = k0 + 32;
        if (k1 < K) {
            a_reg = __ldcg((const uint4*)(A + (size_t)ar * lda + k1 + akq));
            if (wok) {
                const __half* wp = Wt + (size_t)nr * ldk + k1 + koff;
                w_reg0 = *(const uint4*)wp;
                w_reg1 = *(const uint4*)(wp + 8);
            }
        }
        if (act) {
#pragma unroll
            for (int ks = 0; ks < 32; ks += 16) {
                const int gr = lane >> 2, gc = (lane & 3) << 1;
                uint32_t a[2][4], bb[4][2];
#pragma unroll
                for (int mi = 0; mi < 2; mi++) {
                    int row = wm + mi * 16 + gr;
                    a[mi][0] = *(const uint32_t*)&cA[row * 40 + ks + gc];
                    a[mi][1] = *(const uint32_t*)&cA[(row + 8) * 40 + ks + gc];
                    a[mi][2] = *(const uint32_t*)&cA[row * 40 + ks + gc + 8];
                    a[mi][3] = *(const uint32_t*)&cA[(row + 8) * 40 + ks + gc + 8];
                }
#pragma unroll
                for (int nj = 0; nj < 4; nj++) {
                    int n = wn + nj * 8 + gr;
                    bb[nj][0] = *(const uint32_t*)&cW[n * 40 + ks + gc];
                    bb[nj][1] = *(const uint32_t*)&cW[n * 40 + ks + gc + 8];
                }
#pragma unroll
                for (int mi = 0; mi < 2; mi++)
#pragma unroll
                    for (int nj = 0; nj < 4; nj++)
                        mma_fp16(acc[mi][nj], a[mi], bb[nj]);
            }
        }
        buf ^= 1;
    }
    if (!act) return;
    const int gr = lane >> 2, cc = (lane & 3) << 1;
#pragma unroll
    for (int mi = 0; mi < 2; mi++) {
#pragma unroll
        for (int nj = 0; nj < 4; nj++) {
            int row = wm + mi * 16 + gr;
            int col = wn + nj * 8 + cc;
            if (col + 1 < nguard) {
                if (HOUT) {
                    float b0 = bias[col], b1 = bias[col + 1];
                    __half* Ch = (__half*)Cv;
                    *(__half2*)&Ch[(size_t)row * ldc + col] =
                        __floats2half2_rn(acc[mi][nj][0] + b0, acc[mi][nj][1] + b1);
                    *(__half2*)&Ch[(size_t)(row + 8) * ldc + col] =
                        __floats2half2_rn(acc[mi][nj][2] + b0, acc[mi][nj][3] + b1);
                } else {
                    float* C = (float*)Cv;
                    float2 o0 = {acc[mi][nj][0], acc[mi][nj][1]};
                    float2 o1 = {acc[mi][nj][2], acc[mi][nj][3]};
                    *(float2*)&C[(size_t)row * ldc + col] = o0;
                    *(float2*)&C[(size_t)(row + 8) * ldc + col] = o1;
                }
            }
        }
    }
}

#define SMEM_BYTES (2 * 64 * 40 * 2 + 2 * 128 * 40 * 2)   // 30720

// ---------------- att1 = ench @ W_ae + b_ae -> fp16 (standalone) -------------------
__global__ __launch_bounds__(256) void att1h_kernel(const float* __restrict__ bae) {
    __shared__ __align__(16) char smem[SMEM_BYTES];
    __half* sA = (__half*)smem;
    __half* sW = (__half*)(smem + 2 * 64 * 40 * 2);
    int n0 = blockIdx.x * 128;
    int m0 = blockIdx.y * 64;
    fp16_gemm<true>(g_ench + (size_t)m0 * ENCc, ENCc,
                    g_Waet + (size_t)n0 * ENCc, ENCc,
                    g_att1h + (size_t)m0 * Ac + n0, Ac, ENCc, 128, bae + n0,
                    sA, sW, 0);
}

// ---------------- z_emb precompute: all steps (grid 16 x Tc) -----------------------
__global__ __launch_bounds__(256) void zemb_kernel() {
    __shared__ __align__(16) char smem[SMEM_BYTES];
    __half* sA = (__half*)smem;
    __half* sW = (__half*)(smem + 2 * 64 * 40 * 2);
    int n0 = blockIdx.x * 128;
    int t = blockIdx.y;
    fp16_gemm<false>(g_embh + (size_t)t * Bc * Ec, Ec,
                     g_Wxt + (size_t)n0 * KX, KX,
                     g_zpe + (size_t)t * Bc * N4U + n0, N4U, Ec, 128,
                     nullptr, sA, sW, 0);
}

// ---------------- post-loop: logits for all steps (grid 79 x Tc) --------------------
__global__ __launch_bounds__(256) void logits_all_kernel() {
    __shared__ __align__(16) char smem[SMEM_BYTES];
    __half* sA = (__half*)smem;
    __half* sW = (__half*)(smem + 2 * 64 * 40 * 2);
    int n0 = blockIdx.x * 128;
    int t = blockIdx.y;
    int ng = Vc - n0; if (ng > 128) ng = 128;
    int half_t = (g_nb[t] <= 32) ? 1 : 0;
    fp16_gemm<false>(g_chist + (size_t)t * Bc * Uc, Uc,
                     g_Woutt + (size_t)n0 * Uc, Uc,
                     g_logitsA + (size_t)t * Bc * Vc + n0, Vc, Uc, ng,
                     nullptr, sA, sW, half_t);
}

// ---------------- post-loop: vocab softmax for all (b,t), register-resident --------
__global__ __launch_bounds__(256) void softmax_all_kernel(
    const float* __restrict__ bo, float* __restrict__ out_pred) {
    int b = blockIdx.x, t = blockIdx.y;
    int tid = threadIdx.x;  // 256
    if (t >= g_ilen[b]) return;  // pre-zeroed
    __shared__ float s_red[8];
    float4* dst = (float4*)(out_pred + ((size_t)b * Tc + t) * Vc);
    const int NV4 = Vc / 4;  // 2500 = 9*256 + 196
    const float4* lg = (const float4*)(g_logitsA + ((size_t)t * Bc + b) * Vc);
    const float4* bo4 = (const float4*)bo;
    int warp = tid >> 5, lane = tid & 31;
    float4 vals[10];
    float m = -1e30f;
#pragma unroll
    for (int j = 0; j < 10; j++) {
        int i = tid + j * 256;
        if (j < 9 || i < NV4) {
            float4 a = lg[i];
            float4 bb = bo4[i];
            float4 v = {a.x + bb.x, a.y + bb.y, a.z + bb.z, a.w + bb.w};
            vals[j] = v;
            m = fmaxf(m, fmaxf(fmaxf(v.x, v.y), fmaxf(v.z, v.w)));
        }
    }
#pragma unroll
    for (int o = 16; o; o >>= 1) m = fmaxf(m, __shfl_xor_sync(0xffffffff, m, o));
    if (lane == 0) s_red[warp] = m;
    __syncthreads();
    m = s_red[0];
#pragma unroll
    for (int w = 1; w < 8; w++) m = fmaxf(m, s_red[w]);
    float sum = 0.f;
#pragma unroll
    for (int j = 0; j < 10; j++) {
        int i = tid + j * 256;
        if (j < 9 || i < NV4) {
            float4 v = vals[j];
            v.x = expf(v.x - m); v.y = expf(v.y - m);
            v.z = expf(v.z - m); v.w = expf(v.w - m);
            vals[j] = v;
            sum += v.x + v.y + v.z + v.w;
        }
    }
#pragma unroll
    for (int o = 16; o; o >>= 1) sum += __shfl_xor_sync(0xffffffff, sum, o);
    __syncthreads();
    if (lane == 0) s_red[warp] = sum;
    __syncthreads();
    sum = 0.f;
#pragma unroll
    for (int w = 0; w < 8; w++) sum += s_red[w];
    float inv = 1.0f / sum;
#pragma unroll
    for (int j = 0; j < 10; j++) {
        int i = tid + j * 256;
        if (j < 9 || i < NV4) {
            float4 v = vals[j];
            v.x *= inv; v.y *= inv; v.z *= inv; v.w *= inv;
            dst[i] = v;
        }
    }
}

// ---------------- fp32 GEMM for h0/c0 init (partials) -----------------------------
__global__ __launch_bounds__(256) void gemm_k(
    const float* __restrict__ A, int lda,
    const float* __restrict__ W,
    float* __restrict__ out,
    int K, int N, size_t part_stride) {
    __shared__ float As[16][68];
    __shared__ float Ws[16][68];
    const int tid = threadIdx.x;
    const int tx = tid & 15, ty = tid >> 4;
    const int n0 = blockIdx.x * 64;
    const int kchunk = K / gridDim.z;
    const int kbeg = blockIdx.z * kchunk;
    float* ob = out + (size_t)blockIdx.z * part_stride;

    const int lm = tid >> 2;
    const int lq = (tid & 3) << 2;
    const int wk = tid >> 4;
    const int wn = (tid & 15) << 2;

    float acc[4][4] = {};

    for (int k0 = kbeg; k0 < kbeg + kchunk; k0 += 16) {
        float4 av = *(const float4*)(A + (size_t)lm * lda + k0 + lq);
        float4 wv = *(const float4*)(W + (size_t)(k0 + wk) * N + n0 + wn);
        __syncthreads();
        As[lq + 0][lm] = av.x; As[lq + 1][lm] = av.y;
        As[lq + 2][lm] = av.z; As[lq + 3][lm] = av.w;
        *(float4*)&Ws[wk][wn] = wv;
        __syncthreads();
#pragma unroll
        for (int kk = 0; kk < 16; kk++) {
            float4 a = *(const float4*)&As[kk][ty << 2];
            float4 w = *(const float4*)&Ws[kk][tx << 2];
            acc[0][0] = fmaf(a.x, w.x, acc[0][0]); acc[0][1] = fmaf(a.x, w.y, acc[0][1]);
            acc[0][2] = fmaf(a.x, w.z, acc[0][2]); acc[0][3] = fmaf(a.x, w.w, acc[0][3]);
            acc[1][0] = fmaf(a.y, w.x, acc[1][0]); acc[1][1] = fmaf(a.y, w.y, acc[1][1]);
            acc[1][2] = fmaf(a.y, w.z, acc[1][2]); acc[1][3] = fmaf(a.y, w.w, acc[1][3]);
            acc[2][0] = fmaf(a.z, w.x, acc[2][0]); acc[2][1] = fmaf(a.z, w.y, acc[2][1]);
            acc[2][2] = fmaf(a.z, w.z, acc[2][2]); acc[2][3] = fmaf(a.z, w.w, acc[2][3]);
            acc[3][0] = fmaf(a.w, w.x, acc[3][0]); acc[3][1] = fmaf(a.w, w.y, acc[3][1]);
            acc[3][2] = fmaf(a.w, w.z, acc[3][2]); acc[3][3] = fmaf(a.w, w.w, acc[3][3]);
        }
    }
    const int c0 = n0 + (tx << 2);
#pragma unroll
    for (int i = 0; i < 4; i++) {
        int r = (ty << 2) + i;
        float4 o = {acc[i][0], acc[i][1], acc[i][2], acc[i][3]};
        *(float4*)&ob[(size_t)r * N + c0] = o;
    }
}

// ---------------- init h0/c0 from split-K partials + bias (also fp16 copies) ------
__global__ void init_hc_kernel(const float* __restrict__ bm, const float* __restrict__ bc) {
    int b = blockIdx.x, n = threadIdx.x;  // 512
    float h = bm[n], c = bc[n];
#pragma unroll
    for (int s = 0; s < 8; s++) {
        h += g_zp[((size_t)s * Bc + b) * Uc + n];
        c += g_zp[((size_t)(8 + s) * Bc + b) * Uc + n];
    }
    g_h[b * Uc + n] = h;
    g_c[b * Uc + n] = c;
    g_hh[b * Uc + n] = __float2half(h);
    g_ch[b * Uc + n] = __float2half(c);
}

// ---------------- device: attention + softmax + awe (fused, block = b) -------------
__device__ void attn_awe_dev(int b, char* smem,
                             const float* __restrict__ bag,
                             const float* __restrict__ wf,
                             const float* __restrict__ bf,
                             const float* __restrict__ bbeta,
                             float* __restrict__ out_alpha, int t) {
    int tid = threadIdx.x;  // 256
    if (t >= g_ilen[b]) return;  // out_alpha pre-zeroed
    float* s_att2 = (float*)smem;           // 512
    float* s_wf   = s_att2 + 512;           // 512
    float* s_red  = s_wf + 512;             // 8
    float* s_al   = s_red + 8;              // 208 (padded for MLP-16 loop)
    for (int a = tid; a < Ac; a += 256) {
        s_att2[a] = __ldcg(&g_cb[(size_t)b * CBN + a]) + bag[a];
        s_wf[a] = wf[a];
    }
    if (tid >= 196 && tid < 208) s_al[tid] = 0.f;
    __syncthreads();
    int warp = tid >> 5, lane = tid & 31;
    float e = -1e30f;
    if (tid < Pc) {
        const __half* rowp = g_att1h + ((size_t)b * Pc + tid) * Ac;
        float s = 0.f;
#pragma unroll
        for (int i0 = 0; i0 < 64; i0 += 16) {
            uint4 v[16];
#pragma unroll
            for (int q = 0; q < 16; q++) v[q] = *(const uint4*)(rowp + (i0 + q) * 8);
#pragma unroll
            for (int q = 0; q < 16; q++) {
                const __half2* hp = (const __half2*)&v[q];
                int a = (i0 + q) * 8;
#pragma unroll
                for (int j = 0; j < 4; j++) {
                    float2 f = __half22float2(hp[j]);
                    float x0 = f.x + s_att2[a + j * 2];
                    float x1 = f.y + s_att2[a + j * 2 + 1];
                    if (x0 > 0.f) s = fmaf(x0, s_wf[a + j * 2], s);
                    if (x1 > 0.f) s = fmaf(x1, s_wf[a + j * 2 + 1], s);
                }
            }
        }
        e = s + bf[0];
    }
    float m = e;
#pragma unroll
    for (int o = 16; o; o >>= 1) m = fmaxf(m, __shfl_xor_sync(0xffffffff, m, o));
    if (lane == 0) s_red[warp] = m;
    __syncthreads();
    m = s_red[0];
#pragma unroll
    for (int w = 1; w < 8; w++) m = fmaxf(m, s_red[w]);
    float ex = (tid < Pc) ? expf(e - m) : 0.f;
    float sm = ex;
#pragma unroll
    for (int o = 16; o; o >>= 1) sm += __shfl_xor_sync(0xffffffff, sm, o);
    __syncthreads();
    if (lane == 0) s_red[warp] = sm;
    __syncthreads();
    sm = 0.f;
#pragma unroll
    for (int w = 0; w < 8; w++) sm += s_red[w];
    float inv = 1.0f / sm;
    if (tid < Pc) {
        float al = ex * inv;
        s_al[tid] = al;
        out_alpha[((size_t)b * Tc + t) * Pc + tid] = al;
    }
    __syncthreads();
    // awe: each thread owns 8 contiguous ENC cols; 16 rows in flight (MLP 16)
    int e0 = tid * 8;
    const __half* encb = g_ench + (size_t)b * Pc * ENCc + e0;
    float acc[8] = {};
    for (int p = 0; p < 208; p += 16) {
        float l[16];
        uint4 v[16];
#pragma unroll
        for (int q = 0; q < 16; q++) {
            int pr = p + q;
            int prc = pr < Pc ? pr : (Pc - 1);
            l[q] = s_al[pr];  // zeros for 196..207
            v[q] = *(const uint4*)(encb + (size_t)prc * ENCc);
        }
#pragma unroll
        for (int q = 0; q < 16; q++) {
            const __half2* hq = (const __half2*)&v[q];
#pragma unroll
            for (int j = 0; j < 4; j++) {
                float2 f = __half22float2(hq[j]);
                acc[2 * j]     = fmaf(l[q], f.x, acc[2 * j]);
                acc[2 * j + 1] = fmaf(l[q], f.y, acc[2 * j + 1]);
            }
        }
    }
#pragma unroll
    for (int j = 0; j < 8; j += 4) {
        float4 bl = *(const float4*)&bbeta[e0 + j];
        float4 cbv = __ldcg((const float4*)&g_cb[(size_t)b * CBN + Ac + e0 + j]);
        bl.x += cbv.x; bl.y += cbv.y; bl.z += cbv.z; bl.w += cbv.w;
        float o0 = acc[j + 0] / (1.0f + expf(-bl.x));
        float o1 = acc[j + 1] / (1.0f + expf(-bl.y));
        float o2 = acc[j + 2] / (1.0f + expf(-bl.z));
        float o3 = acc[j + 3] / (1.0f + expf(-bl.w));
        __half2 p0 = __floats2half2_rn(o0, o1);
        __half2 p1 = __floats2half2_rn(o2, o3);
        uint2 pack;
        pack.x = *(uint32_t*)&p0;
        pack.y = *(uint32_t*)&p1;
        *(uint2*)&g_aweh[(size_t)b * ENCc + e0 + j] = pack;
    }
}

// ================= persistent loop kernel (131 blocks, 256 threads) ===============
__global__ __launch_bounds__(256) void loop_kernel(
    const float* __restrict__ bag, const float* __restrict__ wf,
    const float* __restrict__ bf, const float* __restrict__ bbeta,
    const float* __restrict__ bl,
    float* __restrict__ out_alpha) {
    __shared__ __align__(16) char smem[SMEM_BYTES];
    __half* sA = (__half*)smem;
    __half* sW = (__half*)(smem + 2 * 64 * 40 * 2);
    const int blk = blockIdx.x;
    const int tid = threadIdx.x;

    for (int t = 0; t < Tc; t++) {
        int nb_t = g_nb[t];
        int half_t = (nb_t <= 32) ? 1 : 0;
        // ---- Phase 1: cb | z_h ----
        if (blk < 20) {
            int n0 = blk * 128;
            fp16_gemm<false>(g_ch, Uc, g_Wcbt + (size_t)n0 * Uc, Uc,
                             g_cb + n0, CBN, Uc, 128, nullptr, sA, sW, half_t);
        } else if (blk < 36) {
            int n0 = (blk - 20) * 128;
            fp16_gemm<false>(g_hh, Uc, g_Wht + (size_t)n0 * Uc, Uc,
                             g_zp + 1 * (size_t)Bc * N4U + n0, N4U, Uc, 128,
                             nullptr, sA, sW, half_t);
        }
        grid_bar();
        // ---- Phase 2: attn+awe(t) ----
        if (blk < 64) attn_awe_dev(blk, smem, bag, wf, bf, bbeta, out_alpha, t);
        grid_bar();
        // ---- Phase 3: z_awe, 8 k-splits x 16 n-tiles ----
        if (blk < 128) {
            int sp = blk >> 4, n0 = (blk & 15) * 128;
            fp16_gemm<false>(g_aweh + sp * 256, ENCc,
                             g_Wxt + (size_t)n0 * KX + Ec + sp * 256, KX,
                             g_zp + (size_t)(2 + sp) * Bc * N4U + n0, N4U,
                             256, 128, nullptr, sA, sW, half_t);
        }
        grid_bar();
        // ---- Phase 4: gates, 128 blocks = (b, n-half of 256) ----
        if (blk < 128) {
            int b = blk >> 1;
            if (t < g_ilen[b]) {
                int n = ((blk & 1) << 8) + tid;  // 0..511
                const float* zpe = g_zpe + ((size_t)t * Bc + b) * N4U;
                float zi = bl[n] + __ldcg(zpe + n);
                float zf = bl[Uc + n] + __ldcg(zpe + Uc + n);
                float zg = bl[2 * Uc + n] + __ldcg(zpe + 2 * Uc + n);
                float zo = bl[3 * Uc + n] + __ldcg(zpe + 3 * Uc + n);
#pragma unroll
                for (int s = 1; s < 10; s++) {
                    const float* zp = g_zp + ((size_t)s * Bc + b) * N4U;
                    zi += __ldcg(zp + n);
                    zf += __ldcg(zp + Uc + n);
                    zg += __ldcg(zp + 2 * Uc + n);
                    zo += __ldcg(zp + 3 * Uc + n);
                }
                float c_old = g_c[b * Uc + n], h_old = g_h[b * Uc + n];
                float si = 1.0f / (1.0f + expf(-zi));
                float sf = 1.0f / (1.0f + expf(-zf));
                float so = 1.0f / (1.0f + expf(-zo));
                float c2 = sf * c_old + si * tanhf(zg);
                float h2 = so * tanhf(c2);
                g_c[b * Uc + n] = c2;
                g_h[b * Uc + n] = h2;
                __half ch = __float2half(c2);
                g_ch[b * Uc + n] = ch;
                g_hh[b * Uc + n] = __float2half(h2);
                g_chist[((size_t)t * Bc + b) * Uc + n] = ch;
            }
        }
        grid_bar();
    }
}

// ---------------- launcher ---------------------------------------------------------
extern "C" void kernel_launch(void* const* d_in, const int* in_sizes, int n_in,
                              void* d_out, int out_size) {
    const float* enc      = (const float*)d_in[0];
    const int*   seqs     = (const int*)  d_in[1];
    const int*   lens     = (const int*)  d_in[2];
    const float* emb_tab  = (const float*)d_in[3];
    const float* W_ae     = (const float*)d_in[4];
    const float* b_ae     = (const float*)d_in[5];
    const float* W_ag     = (const float*)d_in[6];
    const float* b_ag     = (const float*)d_in[7];
    const float* W_af     = (const float*)d_in[8];
    const float* b_af     = (const float*)d_in[9];
    const float* W_x      = (const float*)d_in[10];
    const float* W_h      = (const float*)d_in[11];
    const float* b_lstm   = (const float*)d_in[12];
    const float* W_im     = (const float*)d_in[13];
    const float* b_im     = (const float*)d_in[14];
    const float* W_ic     = (const float*)d_in[15];
    const float* b_ic     = (const float*)d_in[16];
    const float* W_beta   = (const float*)d_in[17];
    const float* b_beta   = (const float*)d_in[18];
    const float* W_out    = (const float*)d_in[19];
    const float* b_out    = (const float*)d_in[20];

    float* out       = (float*)d_out;
    float* out_pred  = out;                                   // [B,T,V]
    float* out_alpha = out_pred + (size_t)Bc * Tc * Vc;       // [B,T,P]
    float* out_seqs  = out_alpha + (size_t)Bc * Tc * Pc;      // [B,S]
    float* out_ilen  = out_seqs + (size_t)Bc * Sc;            // [B]
    float* out_order = out_ilen + Bc;                         // [B]

    float *p_mean, *p_zp;
    cudaGetSymbolAddress((void**)&p_mean, g_mean);
    cudaGetSymbolAddress((void**)&p_zp, g_zp);

    // ---- setup ----
    sort_kernel<<<1, Bc>>>(lens, seqs, out_seqs, out_ilen, out_order);
    {
        size_t tot4 = ((size_t)Bc * Tc * Vc + (size_t)Bc * Tc * Pc) / 4;
        zero_out_kernel<<<(int)((tot4 + 255) / 256), 256>>>(out_pred, out_alpha);
    }
    permute_kernel<<<dim3(Bc, Pc), 256>>>(enc);
    emb_all_kernel<<<dim3(Bc, Tc), 128>>>(emb_tab);
    mean_kernel<<<dim3(Bc, 2), 256>>>();
    convT_all<<<13456, 256>>>(W_ae, W_ag, W_beta, W_out, W_x, W_h);
    gemm_k<<<dim3(Uc / 64, 1, 8), 256>>>(p_mean, ENCc, W_im, p_zp, ENCc, Uc, (size_t)Bc * Uc);
    gemm_k<<<dim3(Uc / 64, 1, 8), 256>>>(p_mean, ENCc, W_ic, p_zp + (size_t)8 * Bc * Uc, ENCc, Uc, (size_t)Bc * Uc);
    init_hc_kernel<<<Bc, Uc>>>(b_im, b_ic);
    att1h_kernel<<<dim3(Ac / 128, (Bc * Pc) / 64), 256>>>(b_ae);
    zemb_kernel<<<dim3(16, Tc), 256>>>();

    // ---- whole time loop in ONE persistent kernel (attention/LSTM path only) ----
    loop_kernel<<<NB, 256>>>(b_ag, W_af, b_af, b_beta, b_lstm, out_alpha);

    // ---- post-loop: all logits + all softmaxes, fully parallel ----
    logits_all_kernel<<<dim3((Vc + 127) / 128, Tc), 256>>>();
    softmax_all_kernel<<<dim3(Bc, Tc), 256>>>(b_out, out_pred);
}

// round 16
// speedup vs baseline: 1.1047x; 1.1047x over previous
#include <cuda_runtime.h>
#include <cuda_fp16.h>
#include <math.h>
#include <stdint.h>

// Problem dims
#define Bc   64
#define Pc   196
#define Sc   22
#define Tc   21
#define Vc   10000
#define Ec   512
#define Ac   512
#define Uc   512
#define ENCc 2048
#define N4U  2048   // 4*U
#define CBN  2560   // A + ENC (att2 | beta combined)
#define KX   2560   // E + ENC (W_x K dim)
#define NB   131    // persistent grid size (single wave on 148 SMs)

// ---------------- scratch (static __device__ arrays; no allocation) -------------
__device__ __half g_ench[Bc * Pc * ENCc];     // sorted encoder fp16 (51.4 MB)
__device__ __half g_att1h[Bc * Pc * Ac];      // att1 fp16 (12.8 MB)
__device__ __half g_Waet[Ac * ENCc];          // W_att_enc^T
__device__ __half g_Wcbt[CBN * Uc];           // [Wag|Wbeta]^T
__device__ __half g_Woutt[Vc * Uc];           // W_out^T
__device__ __half g_Wxt[N4U * KX];            // W_x^T
__device__ __half g_Wht[N4U * Uc];            // W_h^T
__device__ __half g_embh[Tc * Bc * Ec];       // embeddings fp16, all steps
__device__ __half g_ch[Bc * Uc];              // c fp16 (GEMM A operand)
__device__ __half g_hh[Bc * Uc];              // h fp16
__device__ __half g_aweh[Bc * ENCc];          // gated context fp16
__device__ float g_mean[Bc * ENCc];
__device__ float g_h[Bc * Uc];
__device__ float g_c[Bc * Uc];
__device__ float g_cb[Bc * CBN];              // [att2 | beta-logits] (no bias)
__device__ float g_zp[16 * Bc * Uc > 10 * Bc * N4U ? 16 * Bc * Uc : 10 * Bc * N4U];
__device__ float g_zpe[Tc * Bc * N4U];        // precomputed emb@Wx for all steps (11MB)
__device__ float g_logits[Bc * Vc];           // logits (no bias)
__device__ int   g_order[Bc];
__device__ int   g_ilen[Bc];
__device__ int   g_nb[Tc];                    // active rows per step
__device__ int   g_seqs[Bc * Sc];

// ---------------- parallel-flag grid barrier (replay-safe, monotonic) -------------
__device__ volatile int g_flags[NB];
__device__ volatile int g_gen;

__device__ __forceinline__ void grid_bar() {
    __syncthreads();
    int gen = g_gen;
    if (blockIdx.x == 0) {
        if (threadIdx.x == 0) {
            __threadfence();
            g_flags[0] = gen + 1;
        }
        if (threadIdx.x < NB) {
            while (g_flags[threadIdx.x] < gen + 1) {}
        }
        __syncthreads();
        if (threadIdx.x == 0) {
            __threadfence();
            g_gen = gen + 1;
        }
    } else {
        if (threadIdx.x == 0) {
            __threadfence();
            g_flags[blockIdx.x] = gen + 1;
            while (g_gen < gen + 1) {}
            __threadfence();
        }
    }
    __syncthreads();
}

// ---------------- sort: stable argsort(-lens); also per-step active counts --------
__global__ void sort_kernel(const int* __restrict__ lens,
                            const int* __restrict__ seqs,
                            float* __restrict__ out_seqs,
                            float* __restrict__ out_ilen,
                            float* __restrict__ out_order) {
    int tid = threadIdx.x;  // 64 threads
    __shared__ int s_len[Bc];
    s_len[tid] = lens[tid];
    __syncthreads();
    int myL = s_len[tid];
    int rank = 0;
    for (int j = 0; j < Bc; j++) {
        int lj = s_len[j];
        rank += (lj > myL) || (lj == myL && j < tid);
    }
    g_order[rank] = tid;
    __syncthreads();
    int src = g_order[tid];
    int il = s_len[src] - 1;
    g_ilen[tid] = il;
    out_ilen[tid] = (float)il;
    out_order[tid] = (float)src;
    for (int s = 0; s < Sc; s++) {
        int v = seqs[src * Sc + s];
        g_seqs[tid * Sc + s] = v;
        out_seqs[tid * Sc + s] = (float)v;
    }
    __syncthreads();
    if (tid < Tc) {
        int cnt = 0;
        for (int b = 0; b < Bc; b++) cnt += (g_ilen[b] > tid) ? 1 : 0;
        g_nb[tid] = cnt;
    }
}

// ---------------- zero predictions + alphas once (masked slots stay zero) ---------
__global__ void zero_out_kernel(float* __restrict__ out_pred,
                                float* __restrict__ out_alpha) {
    size_t i = (size_t)blockIdx.x * 256 + threadIdx.x;
    float4 z = {0, 0, 0, 0};
    const size_t NP = (size_t)Bc * Tc * Vc / 4;
    const size_t NA = (size_t)Bc * Tc * Pc / 4;
    if (i < NP) ((float4*)out_pred)[i] = z;
    else if (i < NP + NA) ((float4*)out_alpha)[i - NP] = z;
}

// ---------------- permute encoder rows -> fp16 sorted copy ------------------------
__global__ void permute_kernel(const float* __restrict__ enc) {
    int b = blockIdx.x, p = blockIdx.y;
    int src = g_order[b];
    const float4* s = (const float4*)&enc[((size_t)src * Pc + p) * ENCc];
    __half2* dh = (__half2*)&g_ench[((size_t)b * Pc + p) * ENCc];
    for (int i = threadIdx.x; i < ENCc / 4; i += 256) {
        float4 v = s[i];
        dh[i * 2 + 0] = __floats2half2_rn(v.x, v.y);
        dh[i * 2 + 1] = __floats2half2_rn(v.z, v.w);
    }
}

// ---------------- precompute embeddings (fp16) for all timesteps ------------------
__global__ void emb_all_kernel(const float* __restrict__ emb_table) {
    int b = blockIdx.x, t = blockIdx.y;  // 128 threads
    int tok = g_seqs[b * Sc + t];
    float4 v = ((const float4*)(emb_table + (size_t)tok * Ec))[threadIdx.x];
    __half2 h0 = __floats2half2_rn(v.x, v.y);
    __half2 h1 = __floats2half2_rn(v.z, v.w);
    __half2* dst = (__half2*)(g_embh + ((size_t)t * Bc + b) * Ec);
    dst[threadIdx.x * 2 + 0] = h0;
    dst[threadIdx.x * 2 + 1] = h1;
}

// ---------------- mean over pixels (from fp16 copy, fp32 accum) -------------------
__global__ void mean_kernel() {
    int b = blockIdx.x;
    int e0 = blockIdx.y * 1024 + threadIdx.x * 4;
    const __half* encb = g_ench + (size_t)b * Pc * ENCc + e0;
    float4 a0 = {0,0,0,0}, a1 = {0,0,0,0}, a2 = {0,0,0,0}, a3 = {0,0,0,0};
    for (int p = 0; p < Pc; p += 4) {
        uint2 r0 = *(const uint2*)(encb + (size_t)(p + 0) * ENCc);
        uint2 r1 = *(const uint2*)(encb + (size_t)(p + 1) * ENCc);
        uint2 r2 = *(const uint2*)(encb + (size_t)(p + 2) * ENCc);
        uint2 r3 = *(const uint2*)(encb + (size_t)(p + 3) * ENCc);
        float2 f;
        f = __half22float2(*(__half2*)&r0.x); a0.x += f.x; a0.y += f.y;
        f = __half22float2(*(__half2*)&r0.y); a0.z += f.x; a0.w += f.y;
        f = __half22float2(*(__half2*)&r1.x); a1.x += f.x; a1.y += f.y;
        f = __half22float2(*(__half2*)&r1.y); a1.z += f.x; a1.w += f.y;
        f = __half22float2(*(__half2*)&r2.x); a2.x += f.x; a2.y += f.y;
        f = __half22float2(*(__half2*)&r2.y); a2.z += f.x; a2.w += f.y;
        f = __half22float2(*(__half2*)&r3.x); a3.x += f.x; a3.y += f.y;
        f = __half22float2(*(__half2*)&r3.y); a3.z += f.x; a3.w += f.y;
    }
    float4 r;
    r.x = (a0.x + a1.x + a2.x + a3.x) * (1.0f / Pc);
    r.y = (a0.y + a1.y + a2.y + a3.y) * (1.0f / Pc);
    r.z = (a0.z + a1.z + a2.z + a3.z) * (1.0f / Pc);
    r.w = (a0.w + a1.w + a2.w + a3.w) * (1.0f / Pc);
    *(float4*)(g_mean + (size_t)b * ENCc + e0) = r;
}

// ---------------- transpose-convert tile fp32[K,N] -> fp16[N,K] -------------------
__device__ void conv_tile(const float* __restrict__ in, __half* __restrict__ out,
                          int K, int N, int tidx) {
    __shared__ float tile[32][33];
    int gx = (N + 31) >> 5;
    int n0 = (tidx % gx) * 32, k0 = (tidx / gx) * 32;
    int tx = threadIdx.x & 31, ty = threadIdx.x >> 5;  // 256 thr
#pragma unroll
    for (int i = 0; i < 32; i += 8) {
        int k = k0 + ty + i, n = n0 + tx;
        tile[ty + i][tx] = (n < N) ? in[(size_t)k * N + n] : 0.f;
    }
    __syncthreads();
#pragma unroll
    for (int i = 0; i < 32; i += 8) {
        int n = n0 + ty + i;
        if (n < N) out[(size_t)n * K + k0 + tx] = __float2half(tile[tx][ty + i]);
    }
}

__global__ __launch_bounds__(256) void convT_all(
    const float* __restrict__ Wae, const float* __restrict__ Wag,
    const float* __restrict__ Wbeta, const float* __restrict__ Wout,
    const float* __restrict__ Wx, const float* __restrict__ Wh) {
    int b = blockIdx.x;
    if      (b < 1024)  conv_tile(Wae,   g_Waet,                  ENCc, Ac,   b);
    else if (b < 1280)  conv_tile(Wag,   g_Wcbt,                  Uc,   Ac,   b - 1024);
    else if (b < 2304)  conv_tile(Wbeta, g_Wcbt + (size_t)Ac*Uc,  Uc,   ENCc, b - 1280);
    else if (b < 7312)  conv_tile(Wout,  g_Woutt,                 Uc,   Vc,   b - 2304);
    else if (b < 12432) conv_tile(Wx,    g_Wxt,                   KX,   N4U,  b - 7312);
    else                conv_tile(Wh,    g_Wht,                   Uc,   N4U,  b - 12432);
}

// ---------------- fp16 MMA helper --------------------------------------------------
__device__ __forceinline__ void mma_fp16(float* c, const uint32_t* a, const uint32_t* b) {
    asm volatile(
        "mma.sync.aligned.m16n8k16.row.col.f32.f16.f16.f32 "
        "{%0,%1,%2,%3}, {%4,%5,%6,%7}, {%8,%9}, {%0,%1,%2,%3};"
        : "+f"(c[0]), "+f"(c[1]), "+f"(c[2]), "+f"(c[3])
        : "r"(a[0]), "r"(a[1]), "r"(a[2]), "r"(a[3]), "r"(b[0]), "r"(b[1]));
}

// ---- 64x128-tile fp16 GEMM, smem double-buffered, M-adaptive ----------------------
template <bool HOUT>
__device__ void fp16_gemm(const __half* __restrict__ A, int lda,
                          const __half* __restrict__ Wt, int ldk,
                          void* __restrict__ Cv, int ldc,
                          int K, int nguard, const float* __restrict__ bias,
                          __half* __restrict__ sA, __half* __restrict__ sW,
                          int half) {
    const int tid = threadIdx.x;
    const int warp = tid >> 5, lane = tid & 31;
    const int wm = (warp >> 2) << 5;
    const int wn = (warp & 3) << 5;
    const bool act = !(half && wm);

    float acc[2][4][4];
#pragma unroll
    for (int i = 0; i < 2; i++)
#pragma unroll
        for (int j = 0; j < 4; j++)
#pragma unroll
            for (int q = 0; q < 4; q++) acc[i][j][q] = 0.f;

    const int ar = tid >> 2, akq = (tid & 3) << 3;
    const int nr = tid >> 1, koff = (tid & 1) << 4;
    const bool wok = nr < nguard;

    uint4 a_reg = __ldcg((const uint4*)(A + (size_t)ar * lda + akq));
    uint4 w_reg0 = {0, 0, 0, 0}, w_reg1 = {0, 0, 0, 0};
    if (wok) {
        const __half* wp = Wt + (size_t)nr * ldk + koff;
        w_reg0 = *(const uint4*)wp;
        w_reg1 = *(const uint4*)(wp + 8);
    }

    int buf = 0;
    for (int k0 = 0; k0 < K; k0 += 32) {
        __half* cA = sA + buf * (64 * 40);
        __half* cW = sW + buf * (128 * 40);
        *(uint4*)&cA[ar * 40 + akq] = a_reg;
        *(uint4*)&cW[nr * 40 + koff] = w_reg0;
        *(uint4*)&cW[nr * 40 + koff + 8] = w_reg1;
        __syncthreads();
        int k1 = k0 + 32;
        if (k1 < K) {
            a_reg = __ldcg((const uint4*)(A + (size_t)ar * lda + k1 + akq));
            if (wok) {
                const __half* wp = Wt + (size_t)nr * ldk + k1 + koff;
                w_reg0 = *(const uint4*)wp;
                w_reg1 = *(const uint4*)(wp + 8);
            }
        }
        if (act) {
#pragma unroll
            for (int ks = 0; ks < 32; ks += 16) {
                const int gr = lane >> 2, gc = (lane & 3) << 1;
                uint32_t a[2][4], bb[4][2];
#pragma unroll
                for (int mi = 0; mi < 2; mi++) {
                    int row = wm + mi * 16 + gr;
                    a[mi][0] = *(const uint32_t*)&cA[row * 40 + ks + gc];
                    a[mi][1] = *(const uint32_t*)&cA[(row + 8) * 40 + ks + gc];
                    a[mi][2] = *(const uint32_t*)&cA[row * 40 + ks + gc + 8];
                    a[mi][3] = *(const uint32_t*)&cA[(row + 8) * 40 + ks + gc + 8];
                }
#pragma unroll
                for (int nj = 0; nj < 4; nj++) {
                    int n = wn + nj * 8 + gr;
                    bb[nj][0] = *(const uint32_t*)&cW[n * 40 + ks + gc];
                    bb[nj][1] = *(const uint32_t*)&cW[n * 40 + ks + gc + 8];
                }
#pragma unroll
                for (int mi = 0; mi < 2; mi++)
#pragma unroll
                    for (int nj = 0; nj < 4; nj++)
                        mma_fp16(acc[mi][nj], a[mi], bb[nj]);
            }
        }
        buf ^= 1;
    }
    if (!act) return;
    const int gr = lane >> 2, cc = (lane & 3) << 1;
#pragma unroll
    for (int mi = 0; mi < 2; mi++) {
#pragma unroll
        for (int nj = 0; nj < 4; nj++) {
            int row = wm + mi * 16 + gr;
            int col = wn + nj * 8 + cc;
            if (col + 1 < nguard) {
                if (HOUT) {
                    float b0 = bias[col], b1 = bias[col + 1];
                    __half* Ch = (__half*)Cv;
                    *(__half2*)&Ch[(size_t)row * ldc + col] =
                        __floats2half2_rn(acc[mi][nj][0] + b0, acc[mi][nj][1] + b1);
                    *(__half2*)&Ch[(size_t)(row + 8) * ldc + col] =
                        __floats2half2_rn(acc[mi][nj][2] + b0, acc[mi][nj][3] + b1);
                } else {
                    float* C = (float*)Cv;
                    float2 o0 = {acc[mi][nj][0], acc[mi][nj][1]};
                    float2 o1 = {acc[mi][nj][2], acc[mi][nj][3]};
                    *(float2*)&C[(size_t)row * ldc + col] = o0;
                    *(float2*)&C[(size_t)(row + 8) * ldc + col] = o1;
                }
            }
        }
    }
}

#define SMEM_BYTES (2 * 64 * 40 * 2 + 2 * 128 * 40 * 2)   // 30720

// ---------------- att1 = ench @ W_ae + b_ae -> fp16 (standalone) -------------------
__global__ __launch_bounds__(256) void att1h_kernel(const float* __restrict__ bae) {
    __shared__ __align__(16) char smem[SMEM_BYTES];
    __half* sA = (__half*)smem;
    __half* sW = (__half*)(smem + 2 * 64 * 40 * 2);
    int n0 = blockIdx.x * 128;
    int m0 = blockIdx.y * 64;
    fp16_gemm<true>(g_ench + (size_t)m0 * ENCc, ENCc,
                    g_Waet + (size_t)n0 * ENCc, ENCc,
                    g_att1h + (size_t)m0 * Ac + n0, Ac, ENCc, 128, bae + n0,
                    sA, sW, 0);
}

// ---------------- z_emb precompute: all steps (grid 16 x Tc) -----------------------
__global__ __launch_bounds__(256) void zemb_kernel() {
    __shared__ __align__(16) char smem[SMEM_BYTES];
    __half* sA = (__half*)smem;
    __half* sW = (__half*)(smem + 2 * 64 * 40 * 2);
    int n0 = blockIdx.x * 128;
    int t = blockIdx.y;
    fp16_gemm<false>(g_embh + (size_t)t * Bc * Ec, Ec,
                     g_Wxt + (size_t)n0 * KX, KX,
                     g_zpe + (size_t)t * Bc * N4U + n0, N4U, Ec, 128,
                     nullptr, sA, sW, 0);
}

// ---------------- fp32 GEMM for h0/c0 init (partials) -----------------------------
__global__ __launch_bounds__(256) void gemm_k(
    const float* __restrict__ A, int lda,
    const float* __restrict__ W,
    float* __restrict__ out,
    int K, int N, size_t part_stride) {
    __shared__ float As[16][68];
    __shared__ float Ws[16][68];
    const int tid = threadIdx.x;
    const int tx = tid & 15, ty = tid >> 4;
    const int n0 = blockIdx.x * 64;
    const int kchunk = K / gridDim.z;
    const int kbeg = blockIdx.z * kchunk;
    float* ob = out + (size_t)blockIdx.z * part_stride;

    const int lm = tid >> 2;
    const int lq = (tid & 3) << 2;
    const int wk = tid >> 4;
    const int wn = (tid & 15) << 2;

    float acc[4][4] = {};

    for (int k0 = kbeg; k0 < kbeg + kchunk; k0 += 16) {
        float4 av = *(const float4*)(A + (size_t)lm * lda + k0 + lq);
        float4 wv = *(const float4*)(W + (size_t)(k0 + wk) * N + n0 + wn);
        __syncthreads();
        As[lq + 0][lm] = av.x; As[lq + 1][lm] = av.y;
        As[lq + 2][lm] = av.z; As[lq + 3][lm] = av.w;
        *(float4*)&Ws[wk][wn] = wv;
        __syncthreads();
#pragma unroll
        for (int kk = 0; kk < 16; kk++) {
            float4 a = *(const float4*)&As[kk][ty << 2];
            float4 w = *(const float4*)&Ws[kk][tx << 2];
            acc[0][0] = fmaf(a.x, w.x, acc[0][0]); acc[0][1] = fmaf(a.x, w.y, acc[0][1]);
            acc[0][2] = fmaf(a.x, w.z, acc[0][2]); acc[0][3] = fmaf(a.x, w.w, acc[0][3]);
            acc[1][0] = fmaf(a.y, w.x, acc[1][0]); acc[1][1] = fmaf(a.y, w.y, acc[1][1]);
            acc[1][2] = fmaf(a.y, w.z, acc[1][2]); acc[1][3] = fmaf(a.y, w.w, acc[1][3]);
            acc[2][0] = fmaf(a.z, w.x, acc[2][0]); acc[2][1] = fmaf(a.z, w.y, acc[2][1]);
            acc[2][2] = fmaf(a.z, w.z, acc[2][2]); acc[2][3] = fmaf(a.z, w.w, acc[2][3]);
            acc[3][0] = fmaf(a.w, w.x, acc[3][0]); acc[3][1] = fmaf(a.w, w.y, acc[3][1]);
            acc[3][2] = fmaf(a.w, w.z, acc[3][2]); acc[3][3] = fmaf(a.w, w.w, acc[3][3]);
        }
    }
    const int c0 = n0 + (tx << 2);
#pragma unroll
    for (int i = 0; i < 4; i++) {
        int r = (ty << 2) + i;
        float4 o = {acc[i][0], acc[i][1], acc[i][2], acc[i][3]};
        *(float4*)&ob[(size_t)r * N + c0] = o;
    }
}

// ---------------- init h0/c0 from split-K partials + bias (also fp16 copies) ------
__global__ void init_hc_kernel(const float* __restrict__ bm, const float* __restrict__ bc) {
    int b = blockIdx.x, n = threadIdx.x;  // 512
    float h = bm[n], c = bc[n];
#pragma unroll
    for (int s = 0; s < 8; s++) {
        h += g_zp[((size_t)s * Bc + b) * Uc + n];
        c += g_zp[((size_t)(8 + s) * Bc + b) * Uc + n];
    }
    g_h[b * Uc + n] = h;
    g_c[b * Uc + n] = c;
    g_hh[b * Uc + n] = __float2half(h);
    g_ch[b * Uc + n] = __float2half(c);
}

// ---------------- device: attention + softmax + awe (fused, block = b) -------------
__device__ void attn_awe_dev(int b, char* smem,
                             const float* __restrict__ bag,
                             const float* __restrict__ wf,
                             const float* __restrict__ bf,
                             const float* __restrict__ bbeta,
                             float* __restrict__ out_alpha, int t) {
    int tid = threadIdx.x;  // 256
    if (t >= g_ilen[b]) return;  // out_alpha pre-zeroed
    float* s_att2 = (float*)smem;           // 512
    float* s_wf   = s_att2 + 512;           // 512
    float* s_red  = s_wf + 512;             // 8
    float* s_al   = s_red + 8;              // 208 (padded for MLP-16 loop)
    for (int a = tid; a < Ac; a += 256) {
        s_att2[a] = __ldcg(&g_cb[(size_t)b * CBN + a]) + bag[a];
        s_wf[a] = wf[a];
    }
    if (tid >= 196 && tid < 208) s_al[tid] = 0.f;
    __syncthreads();
    int warp = tid >> 5, lane = tid & 31;
    float e = -1e30f;
    if (tid < Pc) {
        const __half* rowp = g_att1h + ((size_t)b * Pc + tid) * Ac;
        float s = 0.f;
#pragma unroll
        for (int i0 = 0; i0 < 64; i0 += 16) {
            uint4 v[16];
#pragma unroll
            for (int q = 0; q < 16; q++) v[q] = *(const uint4*)(rowp + (i0 + q) * 8);
#pragma unroll
            for (int q = 0; q < 16; q++) {
                const __half2* hp = (const __half2*)&v[q];
                int a = (i0 + q) * 8;
#pragma unroll
                for (int j = 0; j < 4; j++) {
                    float2 f = __half22float2(hp[j]);
                    float x0 = f.x + s_att2[a + j * 2];
                    float x1 = f.y + s_att2[a + j * 2 + 1];
                    if (x0 > 0.f) s = fmaf(x0, s_wf[a + j * 2], s);
                    if (x1 > 0.f) s = fmaf(x1, s_wf[a + j * 2 + 1], s);
                }
            }
        }
        e = s + bf[0];
    }
    float m = e;
#pragma unroll
    for (int o = 16; o; o >>= 1) m = fmaxf(m, __shfl_xor_sync(0xffffffff, m, o));
    if (lane == 0) s_red[warp] = m;
    __syncthreads();
    m = s_red[0];
#pragma unroll
    for (int w = 1; w < 8; w++) m = fmaxf(m, s_red[w]);
    float ex = (tid < Pc) ? expf(e - m) : 0.f;
    float sm = ex;
#pragma unroll
    for (int o = 16; o; o >>= 1) sm += __shfl_xor_sync(0xffffffff, sm, o);
    __syncthreads();
    if (lane == 0) s_red[warp] = sm;
    __syncthreads();
    sm = 0.f;
#pragma unroll
    for (int w = 0; w < 8; w++) sm += s_red[w];
    float inv = 1.0f / sm;
    if (tid < Pc) {
        float al = ex * inv;
        s_al[tid] = al;
        out_alpha[((size_t)b * Tc + t) * Pc + tid] = al;
    }
    __syncthreads();
    // awe: each thread owns 8 contiguous ENC cols; 16 rows in flight (MLP 16)
    int e0 = tid * 8;
    const __half* encb = g_ench + (size_t)b * Pc * ENCc + e0;
    float acc[8] = {};
    for (int p = 0; p < 208; p += 16) {
        float l[16];
        uint4 v[16];
#pragma unroll
        for (int q = 0; q < 16; q++) {
            int pr = p + q;
            int prc = pr < Pc ? pr : (Pc - 1);
            l[q] = s_al[pr];  // zeros for 196..207
            v[q] = *(const uint4*)(encb + (size_t)prc * ENCc);
        }
#pragma unroll
        for (int q = 0; q < 16; q++) {
            const __half2* hq = (const __half2*)&v[q];
#pragma unroll
            for (int j = 0; j < 4; j++) {
                float2 f = __half22float2(hq[j]);
                acc[2 * j]     = fmaf(l[q], f.x, acc[2 * j]);
                acc[2 * j + 1] = fmaf(l[q], f.y, acc[2 * j + 1]);
            }
        }
    }
#pragma unroll
    for (int j = 0; j < 8; j += 4) {
        float4 bl = *(const float4*)&bbeta[e0 + j];
        float4 cbv = __ldcg((const float4*)&g_cb[(size_t)b * CBN + Ac + e0 + j]);
        bl.x += cbv.x; bl.y += cbv.y; bl.z += cbv.z; bl.w += cbv.w;
        float o0 = acc[j + 0] / (1.0f + expf(-bl.x));
        float o1 = acc[j + 1] / (1.0f + expf(-bl.y));
        float o2 = acc[j + 2] / (1.0f + expf(-bl.z));
        float o3 = acc[j + 3] / (1.0f + expf(-bl.w));
        __half2 p0 = __floats2half2_rn(o0, o1);
        __half2 p1 = __floats2half2_rn(o2, o3);
        uint2 pack;
        pack.x = *(uint32_t*)&p0;
        pack.y = *(uint32_t*)&p1;
        *(uint2*)&g_aweh[(size_t)b * ENCc + e0 + j] = pack;
    }
}

// ---------------- device: vocab softmax, register-resident (single store) ----------
__device__ void softmax_dev(int b, char* smem, const float* __restrict__ bo,
                            float* __restrict__ out_pred, int tsoft) {
    int tid = threadIdx.x;  // 256
    if (tsoft >= g_ilen[b]) return;  // pre-zeroed
    float4* dst = (float4*)(out_pred + ((size_t)b * Tc + tsoft) * Vc);
    const int NV4 = Vc / 4;  // 2500 = 9*256 + 196
    const float4* lg = (const float4*)(g_logits + (size_t)b * Vc);
    const float4* bo4 = (const float4*)bo;
    float* s_red = (float*)smem;
    int warp = tid >> 5, lane = tid & 31;
    float4 vals[10];
    float m = -1e30f;
#pragma unroll
    for (int j = 0; j < 10; j++) {
        int i = tid + j * 256;
        if (j < 9 || i < NV4) {
            float4 a = __ldcg(lg + i);
            float4 bb = bo4[i];
            float4 v = {a.x + bb.x, a.y + bb.y, a.z + bb.z, a.w + bb.w};
            vals[j] = v;
            m = fmaxf(m, fmaxf(fmaxf(v.x, v.y), fmaxf(v.z, v.w)));
        }
    }
#pragma unroll
    for (int o = 16; o; o >>= 1) m = fmaxf(m, __shfl_xor_sync(0xffffffff, m, o));
    if (lane == 0) s_red[warp] = m;
    __syncthreads();
    m = s_red[0];
#pragma unroll
    for (int w = 1; w < 8; w++) m = fmaxf(m, s_red[w]);
    float sum = 0.f;
#pragma unroll
    for (int j = 0; j < 10; j++) {
        int i = tid + j * 256;
        if (j < 9 || i < NV4) {
            float4 v = vals[j];
            v.x = expf(v.x - m); v.y = expf(v.y - m);
            v.z = expf(v.z - m); v.w = expf(v.w - m);
            vals[j] = v;
            sum += v.x + v.y + v.z + v.w;
        }
    }
#pragma unroll
    for (int o = 16; o; o >>= 1) sum += __shfl_xor_sync(0xffffffff, sum, o);
    __syncthreads();
    if (lane == 0) s_red[warp] = sum;
    __syncthreads();
    sum = 0.f;
#pragma unroll
    for (int w = 0; w < 8; w++) sum += s_red[w];
    float inv = 1.0f / sum;
#pragma unroll
    for (int j = 0; j < 10; j++) {
        int i = tid + j * 256;
        if (j < 9 || i < NV4) {
            float4 v = vals[j];
            v.x *= inv; v.y *= inv; v.z *= inv; v.w *= inv;
            dst[i] = v;
        }
    }
}

// ================= persistent loop kernel (131 blocks, 256 threads) ===============
__global__ __launch_bounds__(256) void loop_kernel(
    const float* __restrict__ bag, const float* __restrict__ wf,
    const float* __restrict__ bf, const float* __restrict__ bbeta,
    const float* __restrict__ bl, const float* __restrict__ bo,
    float* __restrict__ out_alpha, float* __restrict__ out_pred) {
    __shared__ __align__(16) char smem[SMEM_BYTES];
    __half* sA = (__half*)smem;
    __half* sW = (__half*)(smem + 2 * 64 * 40 * 2);
    const int blk = blockIdx.x;
    const int tid = threadIdx.x;

    for (int t = 0; t < Tc; t++) {
        int nb_t = g_nb[t];
        int half_t = (nb_t <= 32) ? 1 : 0;
        int half_prev = (t > 0 && g_nb[t - 1] <= 32) ? 1 : 0;
        // ---- Phase 1: cb | logits(t-1) | z_h ----
        if (blk < 20) {
            int n0 = blk * 128;
            fp16_gemm<false>(g_ch, Uc, g_Wcbt + (size_t)n0 * Uc, Uc,
                             g_cb + n0, CBN, Uc, 128, nullptr, sA, sW, half_t);
        } else if (blk < 99) {
            if (t > 0) {
                int n0 = (blk - 20) * 128;
                int ng = Vc - n0; if (ng > 128) ng = 128;
                fp16_gemm<false>(g_ch, Uc, g_Woutt + (size_t)n0 * Uc, Uc,
                                 g_logits + n0, Vc, Uc, ng, nullptr, sA, sW, half_prev);
            }
        } else if (blk < 115) {
            int n0 = (blk - 99) * 128;
            fp16_gemm<false>(g_hh, Uc, g_Wht + (size_t)n0 * Uc, Uc,
                             g_zp + 1 * (size_t)Bc * N4U + n0, N4U, Uc, 128,
                             nullptr, sA, sW, half_t);
        }
        grid_bar();
        // ---- Phase 2: attn+awe(t) | softmax(t-1) ----
        if (blk < 64) {
            attn_awe_dev(blk, smem, bag, wf, bf, bbeta, out_alpha, t);
        } else if (blk < 128) {
            if (t > 0) softmax_dev(blk - 64, smem, bo, out_pred, t - 1);
        }
        grid_bar();
        // ---- Phase 3: z_awe, 8 k-splits x 16 n-tiles ----
        if (blk < 128) {
            int sp = blk >> 4, n0 = (blk & 15) * 128;
            fp16_gemm<false>(g_aweh + sp * 256, ENCc,
                             g_Wxt + (size_t)n0 * KX + Ec + sp * 256, KX,
                             g_zp + (size_t)(2 + sp) * Bc * N4U + n0, N4U,
                             256, 128, nullptr, sA, sW, half_t);
        }
        grid_bar();
        // ---- Phase 4: gates, 128 blocks = (b, n-half of 256) ----
        if (blk < 128) {
            int b = blk >> 1;
            if (t < g_ilen[b]) {
                int n = ((blk & 1) << 8) + tid;  // 0..511
                const float* zpe = g_zpe + ((size_t)t * Bc + b) * N4U;
                float zi = bl[n] + __ldcg(zpe + n);
                float zf = bl[Uc + n] + __ldcg(zpe + Uc + n);
                float zg = bl[2 * Uc + n] + __ldcg(zpe + 2 * Uc + n);
                float zo = bl[3 * Uc + n] + __ldcg(zpe + 3 * Uc + n);
#pragma unroll
                for (int s = 1; s < 10; s++) {
                    const float* zp = g_zp + ((size_t)s * Bc + b) * N4U;
                    zi += __ldcg(zp + n);
                    zf += __ldcg(zp + Uc + n);
                    zg += __ldcg(zp + 2 * Uc + n);
                    zo += __ldcg(zp + 3 * Uc + n);
                }
                float c_old = g_c[b * Uc + n], h_old = g_h[b * Uc + n];
                float si = 1.0f / (1.0f + expf(-zi));
                float sf = 1.0f / (1.0f + expf(-zf));
                float so = 1.0f / (1.0f + expf(-zo));
                float c2 = sf * c_old + si * tanhf(zg);
                float h2 = so * tanhf(c2);
                g_c[b * Uc + n] = c2;
                g_h[b * Uc + n] = h2;
                g_ch[b * Uc + n] = __float2half(c2);
                g_hh[b * Uc + n] = __float2half(h2);
            }
        }
        grid_bar();
    }
    // ---- tail: logits + softmax for the final step ----
    {
        int half_last = (g_nb[Tc - 1] <= 32) ? 1 : 0;
        if (blk >= 20 && blk < 99) {
            int n0 = (blk - 20) * 128;
            int ng = Vc - n0; if (ng > 128) ng = 128;
            fp16_gemm<false>(g_ch, Uc, g_Woutt + (size_t)n0 * Uc, Uc,
                             g_logits + n0, Vc, Uc, ng, nullptr, sA, sW, half_last);
        }
    }
    grid_bar();
    if (blk >= 64 && blk < 128) softmax_dev(blk - 64, smem, bo, out_pred, Tc - 1);
}

// ---------------- launcher ---------------------------------------------------------
extern "C" void kernel_launch(void* const* d_in, const int* in_sizes, int n_in,
                              void* d_out, int out_size) {
    const float* enc      = (const float*)d_in[0];
    const int*   seqs     = (const int*)  d_in[1];
    const int*   lens     = (const int*)  d_in[2];
    const float* emb_tab  = (const float*)d_in[3];
    const float* W_ae     = (const float*)d_in[4];
    const float* b_ae     = (const float*)d_in[5];
    const float* W_ag     = (const float*)d_in[6];
    const float* b_ag     = (const float*)d_in[7];
    const float* W_af     = (const float*)d_in[8];
    const float* b_af     = (const float*)d_in[9];
    const float* W_x      = (const float*)d_in[10];
    const float* W_h      = (const float*)d_in[11];
    const float* b_lstm   = (const float*)d_in[12];
    const float* W_im     = (const float*)d_in[13];
    const float* b_im     = (const float*)d_in[14];
    const float* W_ic     = (const float*)d_in[15];
    const float* b_ic     = (const float*)d_in[16];
    const float* W_beta   = (const float*)d_in[17];
    const float* b_beta   = (const float*)d_in[18];
    const float* W_out    = (const float*)d_in[19];
    const float* b_out    = (const float*)d_in[20];

    float* out       = (float*)d_out;
    float* out_pred  = out;                                   // [B,T,V]
    float* out_alpha = out_pred + (size_t)Bc * Tc * Vc;       // [B,T,P]
    float* out_seqs  = out_alpha + (size_t)Bc * Tc * Pc;      // [B,S]
    float* out_ilen  = out_seqs + (size_t)Bc * Sc;            // [B]
    float* out_order = out_ilen + Bc;                         // [B]

    float *p_mean, *p_zp;
    cudaGetSymbolAddress((void**)&p_mean, g_mean);
    cudaGetSymbolAddress((void**)&p_zp, g_zp);

    // ---- setup ----
    sort_kernel<<<1, Bc>>>(lens, seqs, out_seqs, out_ilen, out_order);
    {
        size_t tot4 = ((size_t)Bc * Tc * Vc + (size_t)Bc * Tc * Pc) / 4;
        zero_out_kernel<<<(int)((tot4 + 255) / 256), 256>>>(out_pred, out_alpha);
    }
    permute_kernel<<<dim3(Bc, Pc), 256>>>(enc);
    emb_all_kernel<<<dim3(Bc, Tc), 128>>>(emb_tab);
    mean_kernel<<<dim3(Bc, 2), 256>>>();
    convT_all<<<13456, 256>>>(W_ae, W_ag, W_beta, W_out, W_x, W_h);
    gemm_k<<<dim3(Uc / 64, 1, 8), 256>>>(p_mean, ENCc, W_im, p_zp, ENCc, Uc, (size_t)Bc * Uc);
    gemm_k<<<dim3(Uc / 64, 1, 8), 256>>>(p_mean, ENCc, W_ic, p_zp + (size_t)8 * Bc * Uc, ENCc, Uc, (size_t)Bc * Uc);
    init_hc_kernel<<<Bc, Uc>>>(b_im, b_ic);
    att1h_kernel<<<dim3(Ac / 128, (Bc * Pc) / 64), 256>>>(b_ae);
    zemb_kernel<<<dim3(16, Tc), 256>>>();

    // ---- whole time loop in ONE persistent kernel ----
    loop_kernel<<<NB, 256>>>(b_ag, W_af, b_af, b_beta, b_lstm, b_out,
                             out_alpha, out_pred);
}

// round 17
// speedup vs baseline: 1.1173x; 1.0114x over previous
#include <cuda_runtime.h>
#include <cuda_fp16.h>
#include <math.h>
#include <stdint.h>

// Problem dims
#define Bc   64
#define Pc   196
#define Sc   22
#define Tc   21
#define Vc   10000
#define Ec   512
#define Ac   512
#define Uc   512
#define ENCc 2048
#define N4U  2048   // 4*U
#define CBN  2560   // A + ENC (att2 | beta combined)
#define KX   2560   // E + ENC (W_x K dim)
#define NB   131    // persistent grid size (single wave on 148 SMs)

// ---------------- scratch (static __device__ arrays; no allocation) -------------
__device__ __half g_ench[Bc * Pc * ENCc];     // sorted encoder fp16 (51.4 MB)
__device__ __half g_att1h[Bc * Pc * Ac];      // att1 fp16 (12.8 MB)
__device__ __half g_Waet[Ac * ENCc];          // W_att_enc^T
__device__ __half g_Wcbt[CBN * Uc];           // [Wag|Wbeta]^T
__device__ __half g_Woutt[Vc * Uc];           // W_out^T
__device__ __half g_Wxt[N4U * KX];            // W_x^T
__device__ __half g_Wht[N4U * Uc];            // W_h^T
__device__ __half g_embh[Tc * Bc * Ec];       // embeddings fp16, all steps
__device__ __half g_ch[Bc * Uc];              // c fp16 (GEMM A operand)
__device__ __half g_hh[Bc * Uc];              // h fp16
__device__ __half g_aweh[Bc * ENCc];          // gated context fp16
__device__ float g_mean[Bc * ENCc];
__device__ float g_h[Bc * Uc];
__device__ float g_c[Bc * Uc];
__device__ float g_cb[Bc * CBN];              // [att2 | beta-logits] (no bias)
__device__ float g_zp[16 * Bc * Uc > 10 * Bc * N4U ? 16 * Bc * Uc : 10 * Bc * N4U];
__device__ float g_zpe[Tc * Bc * N4U];        // precomputed emb@Wx for all steps (11MB)
__device__ float g_logits[Bc * Vc];           // logits (no bias)
__device__ int   g_order[Bc];
__device__ int   g_ilen[Bc];
__device__ int   g_nb[Tc];                    // active rows per step
__device__ int   g_seqs[Bc * Sc];

// ---------------- parallel-flag grid barrier (replay-safe, monotonic) -------------
__device__ volatile int g_flags[NB];
__device__ volatile int g_gen;

__device__ __forceinline__ void grid_bar() {
    __syncthreads();
    int gen = g_gen;
    if (blockIdx.x == 0) {
        if (threadIdx.x == 0) {
            __threadfence();
            g_flags[0] = gen + 1;
        }
        if (threadIdx.x < NB) {
            while (g_flags[threadIdx.x] < gen + 1) {}
        }
        __syncthreads();
        if (threadIdx.x == 0) {
            __threadfence();
            g_gen = gen + 1;
        }
    } else {
        if (threadIdx.x == 0) {
            __threadfence();
            g_flags[blockIdx.x] = gen + 1;
            while (g_gen < gen + 1) {}
            __threadfence();
        }
    }
    __syncthreads();
}

// ---------------- sort: stable argsort(-lens); also per-step active counts --------
__global__ void sort_kernel(const int* __restrict__ lens,
                            const int* __restrict__ seqs,
                            float* __restrict__ out_seqs,
                            float* __restrict__ out_ilen,
                            float* __restrict__ out_order) {
    int tid = threadIdx.x;  // 64 threads
    __shared__ int s_len[Bc];
    s_len[tid] = lens[tid];
    __syncthreads();
    int myL = s_len[tid];
    int rank = 0;
    for (int j = 0; j < Bc; j++) {
        int lj = s_len[j];
        rank += (lj > myL) || (lj == myL && j < tid);
    }
    g_order[rank] = tid;
    __syncthreads();
    int src = g_order[tid];
    int il = s_len[src] - 1;
    g_ilen[tid] = il;
    out_ilen[tid] = (float)il;
    out_order[tid] = (float)src;
    for (int s = 0; s < Sc; s++) {
        int v = seqs[src * Sc + s];
        g_seqs[tid * Sc + s] = v;
        out_seqs[tid * Sc + s] = (float)v;
    }
    __syncthreads();
    if (tid < Tc) {
        int cnt = 0;
        for (int b = 0; b < Bc; b++) cnt += (g_ilen[b] > tid) ? 1 : 0;
        g_nb[tid] = cnt;
    }
}

// ---------------- transpose-convert tile fp32[K,N] -> fp16[N,K] -------------------
__device__ void conv_tile(const float* __restrict__ in, __half* __restrict__ out,
                          int K, int N, int tidx) {
    __shared__ float tile[32][33];
    int gx = (N + 31) >> 5;
    int n0 = (tidx % gx) * 32, k0 = (tidx / gx) * 32;
    int tx = threadIdx.x & 31, ty = threadIdx.x >> 5;  // 256 thr
#pragma unroll
    for (int i = 0; i < 32; i += 8) {
        int k = k0 + ty + i, n = n0 + tx;
        tile[ty + i][tx] = (n < N) ? in[(size_t)k * N + n] : 0.f;
    }
    __syncthreads();
#pragma unroll
    for (int i = 0; i < 32; i += 8) {
        int n = n0 + ty + i;
        if (n < N) out[(size_t)n * K + k0 + tx] = __float2half(tile[tx][ty + i]);
    }
}

// ---------------- fused setup: zero outputs | permute | emb | convT ----------------
#define ZOB 13383   // zero-out blocks (1024 floats each)
__global__ __launch_bounds__(256) void setup1_kernel(
    const float* __restrict__ enc, const float* __restrict__ emb_table,
    const float* __restrict__ Wae, const float* __restrict__ Wag,
    const float* __restrict__ Wbeta, const float* __restrict__ Wout,
    const float* __restrict__ Wx, const float* __restrict__ Wh,
    float* __restrict__ out_pred, float* __restrict__ out_alpha) {
    int blk = blockIdx.x;
    if (blk < ZOB) {
        size_t i = (size_t)blk * 256 + threadIdx.x;
        float4 z = {0, 0, 0, 0};
        const size_t NP = (size_t)Bc * Tc * Vc / 4;
        const size_t NA = (size_t)Bc * Tc * Pc / 4;
        if (i < NP) ((float4*)out_pred)[i] = z;
        else if (i < NP + NA) ((float4*)out_alpha)[i - NP] = z;
        return;
    }
    blk -= ZOB;
    if (blk < Bc * Pc) {  // permute -> fp16
        int b = blk / Pc, p = blk % Pc;
        int src = g_order[b];
        const float4* s = (const float4*)&enc[((size_t)src * Pc + p) * ENCc];
        __half2* dh = (__half2*)&g_ench[((size_t)b * Pc + p) * ENCc];
        for (int i = threadIdx.x; i < ENCc / 4; i += 256) {
            float4 v = s[i];
            dh[i * 2 + 0] = __floats2half2_rn(v.x, v.y);
            dh[i * 2 + 1] = __floats2half2_rn(v.z, v.w);
        }
        return;
    }
    blk -= Bc * Pc;
    if (blk < Bc * Tc) {  // embeddings
        int b = blk / Tc, t = blk % Tc;
        int tok = g_seqs[b * Sc + t];
        float2 v = ((const float2*)(emb_table + (size_t)tok * Ec))[threadIdx.x];
        ((__half2*)(g_embh + ((size_t)t * Bc + b) * Ec))[threadIdx.x] =
            __floats2half2_rn(v.x, v.y);
        return;
    }
    blk -= Bc * Tc;
    // weight transposes
    if      (blk < 1024)  conv_tile(Wae,   g_Waet,                  ENCc, Ac,   blk);
    else if (blk < 1280)  conv_tile(Wag,   g_Wcbt,                  Uc,   Ac,   blk - 1024);
    else if (blk < 2304)  conv_tile(Wbeta, g_Wcbt + (size_t)Ac*Uc,  Uc,   ENCc, blk - 1280);
    else if (blk < 7312)  conv_tile(Wout,  g_Woutt,                 Uc,   Vc,   blk - 2304);
    else if (blk < 12432) conv_tile(Wx,    g_Wxt,                   KX,   N4U,  blk - 7312);
    else                  conv_tile(Wh,    g_Wht,                   Uc,   N4U,  blk - 12432);
}

// ---------------- mean over pixels (from fp16 copy, fp32 accum) -------------------
__global__ void mean_kernel() {
    int b = blockIdx.x;
    int e0 = blockIdx.y * 1024 + threadIdx.x * 4;
    const __half* encb = g_ench + (size_t)b * Pc * ENCc + e0;
    float4 a0 = {0,0,0,0}, a1 = {0,0,0,0}, a2 = {0,0,0,0}, a3 = {0,0,0,0};
    for (int p = 0; p < Pc; p += 4) {
        uint2 r0 = *(const uint2*)(encb + (size_t)(p + 0) * ENCc);
        uint2 r1 = *(const uint2*)(encb + (size_t)(p + 1) * ENCc);
        uint2 r2 = *(const uint2*)(encb + (size_t)(p + 2) * ENCc);
        uint2 r3 = *(const uint2*)(encb + (size_t)(p + 3) * ENCc);
        float2 f;
        f = __half22float2(*(__half2*)&r0.x); a0.x += f.x; a0.y += f.y;
        f = __half22float2(*(__half2*)&r0.y); a0.z += f.x; a0.w += f.y;
        f = __half22float2(*(__half2*)&r1.x); a1.x += f.x; a1.y += f.y;
        f = __half22float2(*(__half2*)&r1.y); a1.z += f.x; a1.w += f.y;
        f = __half22float2(*(__half2*)&r2.x); a2.x += f.x; a2.y += f.y;
        f = __half22float2(*(__half2*)&r2.y); a2.z += f.x; a2.w += f.y;
        f = __half22float2(*(__half2*)&r3.x); a3.x += f.x; a3.y += f.y;
        f = __half22float2(*(__half2*)&r3.y); a3.z += f.x; a3.w += f.y;
    }
    float4 r;
    r.x = (a0.x + a1.x + a2.x + a3.x) * (1.0f / Pc);
    r.y = (a0.y + a1.y + a2.y + a3.y) * (1.0f / Pc);
    r.z = (a0.z + a1.z + a2.z + a3.z) * (1.0f / Pc);
    r.w = (a0.w + a1.w + a2.w + a3.w) * (1.0f / Pc);
    *(float4*)(g_mean + (size_t)b * ENCc + e0) = r;
}

// ---------------- fp16 MMA helper --------------------------------------------------
__device__ __forceinline__ void mma_fp16(float* c, const uint32_t* a, const uint32_t* b) {
    asm volatile(
        "mma.sync.aligned.m16n8k16.row.col.f32.f16.f16.f32 "
        "{%0,%1,%2,%3}, {%4,%5,%6,%7}, {%8,%9}, {%0,%1,%2,%3};"
        : "+f"(c[0]), "+f"(c[1]), "+f"(c[2]), "+f"(c[3])
        : "r"(a[0]), "r"(a[1]), "r"(a[2]), "r"(a[3]), "r"(b[0]), "r"(b[1]));
}

// ---- 64x128-tile fp16 GEMM, smem double-buffered, M-adaptive ----------------------
template <bool HOUT>
__device__ void fp16_gemm(const __half* __restrict__ A, int lda,
                          const __half* __restrict__ Wt, int ldk,
                          void* __restrict__ Cv, int ldc,
                          int K, int nguard, const float* __restrict__ bias,
                          __half* __restrict__ sA, __half* __restrict__ sW,
                          int half) {
    const int tid = threadIdx.x;
    const int warp = tid >> 5, lane = tid & 31;
    const int wm = (warp >> 2) << 5;
    const int wn = (warp & 3) << 5;
    const bool act = !(half && wm);

    float acc[2][4][4];
#pragma unroll
    for (int i = 0; i < 2; i++)
#pragma unroll
        for (int j = 0; j < 4; j++)
#pragma unroll
            for (int q = 0; q < 4; q++) acc[i][j][q] = 0.f;

    const int ar = tid >> 2, akq = (tid & 3) << 3;
    const int nr = tid >> 1, koff = (tid & 1) << 4;
    const bool wok = nr < nguard;

    uint4 a_reg = __ldcg((const uint4*)(A + (size_t)ar * lda + akq));
    uint4 w_reg0 = {0, 0, 0, 0}, w_reg1 = {0, 0, 0, 0};
    if (wok) {
        const __half* wp = Wt + (size_t)nr * ldk + koff;
        w_reg0 = *(const uint4*)wp;
        w_reg1 = *(const uint4*)(wp + 8);
    }

    int buf = 0;
    for (int k0 = 0; k0 < K; k0 += 32) {
        __half* cA = sA + buf * (64 * 40);
        __half* cW = sW + buf * (128 * 40);
        *(uint4*)&cA[ar * 40 + akq] = a_reg;
        *(uint4*)&cW[nr * 40 + koff] = w_reg0;
        *(uint4*)&cW[nr * 40 + koff + 8] = w_reg1;
        __syncthreads();
        int k1 = k0 + 32;
        if (k1 < K) {
            a_reg = __ldcg((const uint4*)(A + (size_t)ar * lda + k1 + akq));
            if (wok) {
                const __half* wp = Wt + (size_t)nr * ldk + k1 + koff;
                w_reg0 = *(const uint4*)wp;
                w_reg1 = *(const uint4*)(wp + 8);
            }
        }
        if (act) {
#pragma unroll
            for (int ks = 0; ks < 32; ks += 16) {
                const int gr = lane >> 2, gc = (lane & 3) << 1;
                uint32_t a[2][4], bb[4][2];
#pragma unroll
                for (int mi = 0; mi < 2; mi++) {
                    int row = wm + mi * 16 + gr;
                    a[mi][0] = *(const uint32_t*)&cA[row * 40 + ks + gc];
                    a[mi][1] = *(const uint32_t*)&cA[(row + 8) * 40 + ks + gc];
                    a[mi][2] = *(const uint32_t*)&cA[row * 40 + ks + gc + 8];
                    a[mi][3] = *(const uint32_t*)&cA[(row + 8) * 40 + ks + gc + 8];
                }
#pragma unroll
                for (int nj = 0; nj < 4; nj++) {
                    int n = wn + nj * 8 + gr;
                    bb[nj][0] = *(const uint32_t*)&cW[n * 40 + ks + gc];
                    bb[nj][1] = *(const uint32_t*)&cW[n * 40 + ks + gc + 8];
                }
#pragma unroll
                for (int mi = 0; mi < 2; mi++)
#pragma unroll
                    for (int nj = 0; nj < 4; nj++)
                        mma_fp16(acc[mi][nj], a[mi], bb[nj]);
            }
        }
        buf ^= 1;
    }
    if (!act) return;
    const int gr = lane >> 2, cc = (lane & 3) << 1;
#pragma unroll
    for (int mi = 0; mi < 2; mi++) {
#pragma unroll
        for (int nj = 0; nj < 4; nj++) {
            int row = wm + mi * 16 + gr;
            int col = wn + nj * 8 + cc;
            if (col + 1 < nguard) {
                if (HOUT) {
                    float b0 = bias[col], b1 = bias[col + 1];
                    __half* Ch = (__half*)Cv;
                    *(__half2*)&Ch[(size_t)row * ldc + col] =
                        __floats2half2_rn(acc[mi][nj][0] + b0, acc[mi][nj][1] + b1);
                    *(__half2*)&Ch[(size_t)(row + 8) * ldc + col] =
                        __floats2half2_rn(acc[mi][nj][2] + b0, acc[mi][nj][3] + b1);
                } else {
                    float* C = (float*)Cv;
                    float2 o0 = {acc[mi][nj][0], acc[mi][nj][1]};
                    float2 o1 = {acc[mi][nj][2], acc[mi][nj][3]};
                    *(float2*)&C[(size_t)row * ldc + col] = o0;
                    *(float2*)&C[(size_t)(row + 8) * ldc + col] = o1;
                }
            }
        }
    }
}

#define SMEM_BYTES (2 * 64 * 40 * 2 + 2 * 128 * 40 * 2)   // 30720

// ---------------- att1 = ench @ W_ae + b_ae -> fp16 (standalone) -------------------
__global__ __launch_bounds__(256) void att1h_kernel(const float* __restrict__ bae) {
    __shared__ __align__(16) char smem[SMEM_BYTES];
    __half* sA = (__half*)smem;
    __half* sW = (__half*)(smem + 2 * 64 * 40 * 2);
    int n0 = blockIdx.x * 128;
    int m0 = blockIdx.y * 64;
    fp16_gemm<true>(g_ench + (size_t)m0 * ENCc, ENCc,
                    g_Waet + (size_t)n0 * ENCc, ENCc,
                    g_att1h + (size_t)m0 * Ac + n0, Ac, ENCc, 128, bae + n0,
                    sA, sW, 0);
}

// ---------------- z_emb precompute: all steps (grid 16 x Tc) -----------------------
__global__ __launch_bounds__(256) void zemb_kernel() {
    __shared__ __align__(16) char smem[SMEM_BYTES];
    __half* sA = (__half*)smem;
    __half* sW = (__half*)(smem + 2 * 64 * 40 * 2);
    int n0 = blockIdx.x * 128;
    int t = blockIdx.y;
    fp16_gemm<false>(g_embh + (size_t)t * Bc * Ec, Ec,
                     g_Wxt + (size_t)n0 * KX, KX,
                     g_zpe + (size_t)t * Bc * N4U + n0, N4U, Ec, 128,
                     nullptr, sA, sW, 0);
}

// ---------------- fp32 GEMM for h0/c0 init (partials) -----------------------------
__global__ __launch_bounds__(256) void gemm_k(
    const float* __restrict__ A, int lda,
    const float* __restrict__ W,
    float* __restrict__ out,
    int K, int N, size_t part_stride) {
    __shared__ float As[16][68];
    __shared__ float Ws[16][68];
    const int tid = threadIdx.x;
    const int tx = tid & 15, ty = tid >> 4;
    const int n0 = blockIdx.x * 64;
    const int kchunk = K / gridDim.z;
    const int kbeg = blockIdx.z * kchunk;
    float* ob = out + (size_t)blockIdx.z * part_stride;

    const int lm = tid >> 2;
    const int lq = (tid & 3) << 2;
    const int wk = tid >> 4;
    const int wn = (tid & 15) << 2;

    float acc[4][4] = {};

    for (int k0 = kbeg; k0 < kbeg + kchunk; k0 += 16) {
        float4 av = *(const float4*)(A + (size_t)lm * lda + k0 + lq);
        float4 wv = *(const float4*)(W + (size_t)(k0 + wk) * N + n0 + wn);
        __syncthreads();
        As[lq + 0][lm] = av.x; As[lq + 1][lm] = av.y;
        As[lq + 2][lm] = av.z; As[lq + 3][lm] = av.w;
        *(float4*)&Ws[wk][wn] = wv;
        __syncthreads();
#pragma unroll
        for (int kk = 0; kk < 16; kk++) {
            float4 a = *(const float4*)&As[kk][ty << 2];
            float4 w = *(const float4*)&Ws[kk][tx << 2];
            acc[0][0] = fmaf(a.x, w.x, acc[0][0]); acc[0][1] = fmaf(a.x, w.y, acc[0][1]);
            acc[0][2] = fmaf(a.x, w.z, acc[0][2]); acc[0][3] = fmaf(a.x, w.w, acc[0][3]);
            acc[1][0] = fmaf(a.y, w.x, acc[1][0]); acc[1][1] = fmaf(a.y, w.y, acc[1][1]);
            acc[1][2] = fmaf(a.y, w.z, acc[1][2]); acc[1][3] = fmaf(a.y, w.w, acc[1][3]);
            acc[2][0] = fmaf(a.z, w.x, acc[2][0]); acc[2][1] = fmaf(a.z, w.y, acc[2][1]);
            acc[2][2] = fmaf(a.z, w.z, acc[2][2]); acc[2][3] = fmaf(a.z, w.w, acc[2][3]);
            acc[3][0] = fmaf(a.w, w.x, acc[3][0]); acc[3][1] = fmaf(a.w, w.y, acc[3][1]);
            acc[3][2] = fmaf(a.w, w.z, acc[3][2]); acc[3][3] = fmaf(a.w, w.w, acc[3][3]);
        }
    }
    const int c0 = n0 + (tx << 2);
#pragma unroll
    for (int i = 0; i < 4; i++) {
        int r = (ty << 2) + i;
        float4 o = {acc[i][0], acc[i][1], acc[i][2], acc[i][3]};
        *(float4*)&ob[(size_t)r * N + c0] = o;
    }
}

// ---------------- init h0/c0 from split-K partials + bias (also fp16 copies) ------
__global__ void init_hc_kernel(const float* __restrict__ bm, const float* __restrict__ bc) {
    int b = blockIdx.x, n = threadIdx.x;  // 512
    float h = bm[n], c = bc[n];
#pragma unroll
    for (int s = 0; s < 8; s++) {
        h += g_zp[((size_t)s * Bc + b) * Uc + n];
        c += g_zp[((size_t)(8 + s) * Bc + b) * Uc + n];
    }
    g_h[b * Uc + n] = h;
    g_c[b * Uc + n] = c;
    g_hh[b * Uc + n] = __float2half(h);
    g_ch[b * Uc + n] = __float2half(c);
}

// ---------------- helpers for pipelined attention ----------------------------------
__device__ __forceinline__ float score_batch(float s, const uint4* v, int abase,
                                             const float* s_att2, const float* s_wf) {
#pragma unroll
    for (int q = 0; q < 16; q++) {
        const __half2* hp = (const __half2*)&v[q];
        int a = abase + q * 8;
#pragma unroll
        for (int j = 0; j < 4; j++) {
            float2 f = __half22float2(hp[j]);
            float x0 = f.x + s_att2[a + j * 2];
            float x1 = f.y + s_att2[a + j * 2 + 1];
            if (x0 > 0.f) s = fmaf(x0, s_wf[a + j * 2], s);
            if (x1 > 0.f) s = fmaf(x1, s_wf[a + j * 2 + 1], s);
        }
    }
    return s;
}
__device__ __forceinline__ void awe_load(const __half* encb, const float* s_al,
                                         int p, uint4* v, float* l) {
#pragma unroll
    for (int q = 0; q < 16; q++) {
        int pr = p + q;
        int prc = pr < Pc ? pr : (Pc - 1);
        l[q] = s_al[pr];
        v[q] = *(const uint4*)(encb + (size_t)prc * ENCc);
    }
}
__device__ __forceinline__ void awe_acc(float* acc, const uint4* v, const float* l) {
#pragma unroll
    for (int q = 0; q < 16; q++) {
        const __half2* hq = (const __half2*)&v[q];
#pragma unroll
        for (int j = 0; j < 4; j++) {
            float2 f = __half22float2(hq[j]);
            acc[2 * j]     = fmaf(l[q], f.x, acc[2 * j]);
            acc[2 * j + 1] = fmaf(l[q], f.y, acc[2 * j + 1]);
        }
    }
}

// ---------------- device: attention + softmax + awe (fused, block = b) -------------
__device__ void attn_awe_dev(int b, char* smem,
                             const float* __restrict__ bag,
                             const float* __restrict__ wf,
                             const float* __restrict__ bf,
                             const float* __restrict__ bbeta,
                             float* __restrict__ out_alpha, int t) {
    int tid = threadIdx.x;  // 256
    if (t >= g_ilen[b]) return;  // out_alpha pre-zeroed
    float* s_att2 = (float*)smem;           // 512
    float* s_wf   = s_att2 + 512;           // 512
    float* s_red  = s_wf + 512;             // 8
    float* s_al   = s_red + 8;              // 208 (padded)
    for (int a = tid; a < Ac; a += 256) {
        s_att2[a] = __ldcg(&g_cb[(size_t)b * CBN + a]) + bag[a];
        s_wf[a] = wf[a];
    }
    if (tid >= 196 && tid < 208) s_al[tid] = 0.f;
    __syncthreads();
    int warp = tid >> 5, lane = tid & 31;
    float e = -1e30f;
    if (tid < Pc) {
        const __half* rowp = g_att1h + ((size_t)b * Pc + tid) * Ac;
        float s = 0.f;
        uint4 va[16], vb[16];
#pragma unroll
        for (int q = 0; q < 16; q++) va[q] = *(const uint4*)(rowp + q * 8);
        // 4 batches, double-buffered
#pragma unroll
        for (int q = 0; q < 16; q++) vb[q] = *(const uint4*)(rowp + (16 + q) * 8);
        s = score_batch(s, va, 0, s_att2, s_wf);
#pragma unroll
        for (int q = 0; q < 16; q++) va[q] = *(const uint4*)(rowp + (32 + q) * 8);
        s = score_batch(s, vb, 128, s_att2, s_wf);
#pragma unroll
        for (int q = 0; q < 16; q++) vb[q] = *(const uint4*)(rowp + (48 + q) * 8);
        s = score_batch(s, va, 256, s_att2, s_wf);
        s = score_batch(s, vb, 384, s_att2, s_wf);
        e = s + bf[0];
    }
    float m = e;
#pragma unroll
    for (int o = 16; o; o >>= 1) m = fmaxf(m, __shfl_xor_sync(0xffffffff, m, o));
    if (lane == 0) s_red[warp] = m;
    __syncthreads();
    m = s_red[0];
#pragma unroll
    for (int w = 1; w < 8; w++) m = fmaxf(m, s_red[w]);
    float ex = (tid < Pc) ? expf(e - m) : 0.f;
    float sm = ex;
#pragma unroll
    for (int o = 16; o; o >>= 1) sm += __shfl_xor_sync(0xffffffff, sm, o);
    __syncthreads();
    if (lane == 0) s_red[warp] = sm;
    __syncthreads();
    sm = 0.f;
#pragma unroll
    for (int w = 0; w < 8; w++) sm += s_red[w];
    float inv = 1.0f / sm;
    if (tid < Pc) {
        float al = ex * inv;
        s_al[tid] = al;
        out_alpha[((size_t)b * Tc + t) * Pc + tid] = al;
    }
    __syncthreads();
    // awe: 13 batches of 16 rows, double-buffered prefetch
    int e0 = tid * 8;
    const __half* encb = g_ench + (size_t)b * Pc * ENCc + e0;
    float acc[8] = {};
    uint4 va[16], vb[16];
    float la[16], lb[16];
    awe_load(encb, s_al, 0, va, la);
#pragma unroll
    for (int pb = 0; pb < 13; pb++) {
        if ((pb & 1) == 0) {
            if (pb < 12) awe_load(encb, s_al, (pb + 1) * 16, vb, lb);
            awe_acc(acc, va, la);
        } else {
            if (pb < 12) awe_load(encb, s_al, (pb + 1) * 16, va, la);
            awe_acc(acc, vb, lb);
        }
    }
#pragma unroll
    for (int j = 0; j < 8; j += 4) {
        float4 bl = *(const float4*)&bbeta[e0 + j];
        float4 cbv = __ldcg((const float4*)&g_cb[(size_t)b * CBN + Ac + e0 + j]);
        bl.x += cbv.x; bl.y += cbv.y; bl.z += cbv.z; bl.w += cbv.w;
        float o0 = acc[j + 0] / (1.0f + expf(-bl.x));
        float o1 = acc[j + 1] / (1.0f + expf(-bl.y));
        float o2 = acc[j + 2] / (1.0f + expf(-bl.z));
        float o3 = acc[j + 3] / (1.0f + expf(-bl.w));
        __half2 p0 = __floats2half2_rn(o0, o1);
        __half2 p1 = __floats2half2_rn(o2, o3);
        uint2 pack;
        pack.x = *(uint32_t*)&p0;
        pack.y = *(uint32_t*)&p1;
        *(uint2*)&g_aweh[(size_t)b * ENCc + e0 + j] = pack;
    }
}

// ---------------- device: vocab softmax, register-resident (single store) ----------
__device__ void softmax_dev(int b, char* smem, const float* __restrict__ bo,
                            float* __restrict__ out_pred, int tsoft) {
    int tid = threadIdx.x;  // 256
    if (tsoft >= g_ilen[b]) return;  // pre-zeroed
    float4* dst = (float4*)(out_pred + ((size_t)b * Tc + tsoft) * Vc);
    const int NV4 = Vc / 4;  // 2500 = 9*256 + 196
    const float4* lg = (const float4*)(g_logits + (size_t)b * Vc);
    const float4* bo4 = (const float4*)bo;
    float* s_red = (float*)smem;
    int warp = tid >> 5, lane = tid & 31;
    float4 vals[10];
    float m = -1e30f;
#pragma unroll
    for (int j = 0; j < 10; j++) {
        int i = tid + j * 256;
        if (j < 9 || i < NV4) {
            float4 a = __ldcg(lg + i);
            float4 bb = bo4[i];
            float4 v = {a.x + bb.x, a.y + bb.y, a.z + bb.z, a.w + bb.w};
            vals[j] = v;
            m = fmaxf(m, fmaxf(fmaxf(v.x, v.y), fmaxf(v.z, v.w)));
        }
    }
#pragma unroll
    for (int o = 16; o; o >>= 1) m = fmaxf(m, __shfl_xor_sync(0xffffffff, m, o));
    if (lane == 0) s_red[warp] = m;
    __syncthreads();
    m = s_red[0];
#pragma unroll
    for (int w = 1; w < 8; w++) m = fmaxf(m, s_red[w]);
    float sum = 0.f;
#pragma unroll
    for (int j = 0; j < 10; j++) {
        int i = tid + j * 256;
        if (j < 9 || i < NV4) {
            float4 v = vals[j];
            v.x = expf(v.x - m); v.y = expf(v.y - m);
            v.z = expf(v.z - m); v.w = expf(v.w - m);
            vals[j] = v;
            sum += v.x + v.y + v.z + v.w;
        }
    }
#pragma unroll
    for (int o = 16; o; o >>= 1) sum += __shfl_xor_sync(0xffffffff, sum, o);
    __syncthreads();
    if (lane == 0) s_red[warp] = sum;
    __syncthreads();
    sum = 0.f;
#pragma unroll
    for (int w = 0; w < 8; w++) sum += s_red[w];
    float inv = 1.0f / sum;
#pragma unroll
    for (int j = 0; j < 10; j++) {
        int i = tid + j * 256;
        if (j < 9 || i < NV4) {
            float4 v = vals[j];
            v.x *= inv; v.y *= inv; v.z *= inv; v.w *= inv;
            dst[i] = v;
        }
    }
}

// ================= persistent loop kernel (131 blocks, 256 threads) ===============
__global__ __launch_bounds__(256) void loop_kernel(
    const float* __restrict__ bag, const float* __restrict__ wf,
    const float* __restrict__ bf, const float* __restrict__ bbeta,
    const float* __restrict__ bl, const float* __restrict__ bo,
    float* __restrict__ out_alpha, float* __restrict__ out_pred) {
    __shared__ __align__(16) char smem[SMEM_BYTES];
    __half* sA = (__half*)smem;
    __half* sW = (__half*)(smem + 2 * 64 * 40 * 2);
    const int blk = blockIdx.x;
    const int tid = threadIdx.x;

    for (int t = 0; t < Tc; t++) {
        int nb_t = g_nb[t];
        int half_t = (nb_t <= 32) ? 1 : 0;
        int half_prev = (t > 0 && g_nb[t - 1] <= 32) ? 1 : 0;
        // ---- Phase 1: cb | logits(t-1) | z_h ----
        if (blk < 20) {
            int n0 = blk * 128;
            fp16_gemm<false>(g_ch, Uc, g_Wcbt + (size_t)n0 * Uc, Uc,
                             g_cb + n0, CBN, Uc, 128, nullptr, sA, sW, half_t);
        } else if (blk < 99) {
            if (t > 0) {
                int n0 = (blk - 20) * 128;
                int ng = Vc - n0; if (ng > 128) ng = 128;
                fp16_gemm<false>(g_ch, Uc, g_Woutt + (size_t)n0 * Uc, Uc,
                                 g_logits + n0, Vc, Uc, ng, nullptr, sA, sW, half_prev);
            }
        } else if (blk < 115) {
            int n0 = (blk - 99) * 128;
            fp16_gemm<false>(g_hh, Uc, g_Wht + (size_t)n0 * Uc, Uc,
                             g_zp + 1 * (size_t)Bc * N4U + n0, N4U, Uc, 128,
                             nullptr, sA, sW, half_t);
        }
        grid_bar();
        // ---- Phase 2: attn+awe(t) | softmax(t-1) ----
        if (blk < 64) {
            attn_awe_dev(blk, smem, bag, wf, bf, bbeta, out_alpha, t);
        } else if (blk < 128) {
            if (t > 0) softmax_dev(blk - 64, smem, bo, out_pred, t - 1);
        }
        grid_bar();
        // ---- Phase 3: z_awe, 8 k-splits x 16 n-tiles ----
        if (blk < 128) {
            int sp = blk >> 4, n0 = (blk & 15) * 128;
            fp16_gemm<false>(g_aweh + sp * 256, ENCc,
                             g_Wxt + (size_t)n0 * KX + Ec + sp * 256, KX,
                             g_zp + (size_t)(2 + sp) * Bc * N4U + n0, N4U,
                             256, 128, nullptr, sA, sW, half_t);
        }
        grid_bar();
        // ---- Phase 4: gates, 128 blocks = (b, n-half of 256) ----
        if (blk < 128) {
            int b = blk >> 1;
            if (t < g_ilen[b]) {
                int n = ((blk & 1) << 8) + tid;  // 0..511
                const float* zpe = g_zpe + ((size_t)t * Bc + b) * N4U;
                float zi = bl[n] + __ldcg(zpe + n);
                float zf = bl[Uc + n] + __ldcg(zpe + Uc + n);
                float zg = bl[2 * Uc + n] + __ldcg(zpe + 2 * Uc + n);
                float zo = bl[3 * Uc + n] + __ldcg(zpe + 3 * Uc + n);
#pragma unroll
                for (int s = 1; s < 10; s++) {
                    const float* zp = g_zp + ((size_t)s * Bc + b) * N4U;
                    zi += __ldcg(zp + n);
                    zf += __ldcg(zp + Uc + n);
                    zg += __ldcg(zp + 2 * Uc + n);
                    zo += __ldcg(zp + 3 * Uc + n);
                }
                float c_old = g_c[b * Uc + n], h_old = g_h[b * Uc + n];
                float si = 1.0f / (1.0f + expf(-zi));
                float sf = 1.0f / (1.0f + expf(-zf));
                float so = 1.0f / (1.0f + expf(-zo));
                float c2 = sf * c_old + si * tanhf(zg);
                float h2 = so * tanhf(c2);
                g_c[b * Uc + n] = c2;
                g_h[b * Uc + n] = h2;
                g_ch[b * Uc + n] = __float2half(c2);
                g_hh[b * Uc + n] = __float2half(h2);
            }
        }
        grid_bar();
    }
    // ---- tail: logits + softmax for the final step ----
    {
        int half_last = (g_nb[Tc - 1] <= 32) ? 1 : 0;
        if (blk >= 20 && blk < 99) {
            int n0 = (blk - 20) * 128;
            int ng = Vc - n0; if (ng > 128) ng = 128;
            fp16_gemm<false>(g_ch, Uc, g_Woutt + (size_t)n0 * Uc, Uc,
                             g_logits + n0, Vc, Uc, ng, nullptr, sA, sW, half_last);
        }
    }
    grid_bar();
    if (blk >= 64 && blk < 128) softmax_dev(blk - 64, smem, bo, out_pred, Tc - 1);
}

// ---------------- launcher ---------------------------------------------------------
extern "C" void kernel_launch(void* const* d_in, const int* in_sizes, int n_in,
                              void* d_out, int out_size) {
    const float* enc      = (const float*)d_in[0];
    const int*   seqs     = (const int*)  d_in[1];
    const int*   lens     = (const int*)  d_in[2];
    const float* emb_tab  = (const float*)d_in[3];
    const float* W_ae     = (const float*)d_in[4];
    const float* b_ae     = (const float*)d_in[5];
    const float* W_ag     = (const float*)d_in[6];
    const float* b_ag     = (const float*)d_in[7];
    const float* W_af     = (const float*)d_in[8];
    const float* b_af     = (const float*)d_in[9];
    const float* W_x      = (const float*)d_in[10];
    const float* W_h      = (const float*)d_in[11];
    const float* b_lstm   = (const float*)d_in[12];
    const float* W_im     = (const float*)d_in[13];
    const float* b_im     = (const float*)d_in[14];
    const float* W_ic     = (const float*)d_in[15];
    const float* b_ic     = (const float*)d_in[16];
    const float* W_beta   = (const float*)d_in[17];
    const float* b_beta   = (const float*)d_in[18];
    const float* W_out    = (const float*)d_in[19];
    const float* b_out    = (const float*)d_in[20];

    float* out       = (float*)d_out;
    float* out_pred  = out;                                   // [B,T,V]
    float* out_alpha = out_pred + (size_t)Bc * Tc * Vc;       // [B,T,P]
    float* out_seqs  = out_alpha + (size_t)Bc * Tc * Pc;      // [B,S]
    float* out_ilen  = out_seqs + (size_t)Bc * Sc;            // [B]
    float* out_order = out_ilen + Bc;                         // [B]

    float *p_mean, *p_zp;
    cudaGetSymbolAddress((void**)&p_mean, g_mean);
    cudaGetSymbolAddress((void**)&p_zp, g_zp);

    // ---- setup ----
    sort_kernel<<<1, Bc>>>(lens, seqs, out_seqs, out_ilen, out_order);
    setup1_kernel<<<ZOB + Bc * Pc + Bc * Tc + 13456, 256>>>(
        enc, emb_tab, W_ae, W_ag, W_beta, W_out, W_x, W_h, out_pred, out_alpha);
    mean_kernel<<<dim3(Bc, 2), 256>>>();
    gemm_k<<<dim3(Uc / 64, 1, 8), 256>>>(p_mean, ENCc, W_im, p_zp, ENCc, Uc, (size_t)Bc * Uc);
    gemm_k<<<dim3(Uc / 64, 1, 8), 256>>>(p_mean, ENCc, W_ic, p_zp + (size_t)8 * Bc * Uc, ENCc, Uc, (size_t)Bc * Uc);
    init_hc_kernel<<<Bc, Uc>>>(b_im, b_ic);
    att1h_kernel<<<dim3(Ac / 128, (Bc * Pc) / 64), 256>>>(b_ae);
    zemb_kernel<<<dim3(16, Tc), 256>>>();

    // ---- whole time loop in ONE persistent kernel ----
    loop_kernel<<<NB, 256>>>(b_ag, W_af, b_af, b_beta, b_lstm, b_out,
                             out_alpha, out_pred);
}